// round 7
// baseline (speedup 1.0000x reference)
#include <cuda_runtime.h>
#include <cuda_bf16.h>
#include <cstdint>

// Problem dims
#define BATCH 8
#define SEQ   2048
#define EMB   1024
#define HEAD  128
#define MROWS (BATCH * SEQ)     // 16384
#define NTILES (MROWS / 128)    // 128
#define TILE_ELE (128 * 128)

// Pre-split bf16 projected tensors, row-major per 128x128 tile.
// Q tiles: [m][h];  K tiles: [n][h];  V tiles: TRANSPOSED [h][n].
__device__ __nv_bfloat16 g_q_hi[NTILES * TILE_ELE];
__device__ __nv_bfloat16 g_q_lo[NTILES * TILE_ELE];
__device__ __nv_bfloat16 g_k_hi[NTILES * TILE_ELE];
__device__ __nv_bfloat16 g_k_lo[NTILES * TILE_ELE];
__device__ __nv_bfloat16 g_v_hi[NTILES * TILE_ELE];
__device__ __nv_bfloat16 g_v_lo[NTILES * TILE_ELE];

// Pre-split weights: [w][n][k], k contiguous
__device__ __nv_bfloat16 g_w_hi[3 * 128 * 1024];
__device__ __nv_bfloat16 g_w_lo[3 * 128 * 1024];

// Partial O accumulators for split-K chunks (qt >= 8)
__device__ float g_opart[BATCH * 8 * TILE_ELE];

// Chunk schedule: 24 chunks per batch, longest first.
__constant__ int c_qt[24] = {15,15,14, 7,14,13,13,12, 6,12,11,11,10, 5,10, 9, 9, 8, 4, 8, 3, 2, 1, 0};
__constant__ int c_j0[24] = { 0, 8, 0, 0, 8, 0, 7, 0, 0, 7, 0, 6, 0, 0, 6, 0, 5, 0, 0, 5, 0, 0, 0, 0};
__constant__ int c_j1[24] = { 8,16, 8, 8,15, 7,14, 7, 7,13, 6,12, 6, 6,11, 5,10, 5, 5, 9, 4, 3, 2, 1};

// ---------------------------------------------------------------------------
// PTX helpers (family-generic)
// ---------------------------------------------------------------------------
__device__ __forceinline__ uint32_t smem_u32(const void* p) {
    uint32_t a;
    asm("{ .reg .u64 t; cvta.to.shared.u64 t, %1; cvt.u32.u64 %0, t; }"
        : "=r"(a) : "l"(p));
    return a;
}

__device__ __forceinline__ void mma16816(float* c,
    uint32_t a0, uint32_t a1, uint32_t a2, uint32_t a3,
    uint32_t b0, uint32_t b1)
{
    asm volatile(
        "mma.sync.aligned.m16n8k16.row.col.f32.bf16.bf16.f32 "
        "{%0,%1,%2,%3}, {%4,%5,%6,%7}, {%8,%9}, {%0,%1,%2,%3};"
        : "+f"(c[0]), "+f"(c[1]), "+f"(c[2]), "+f"(c[3])
        : "r"(a0), "r"(a1), "r"(a2), "r"(a3), "r"(b0), "r"(b1));
}

__device__ __forceinline__ void ldm_x4(uint32_t& r0, uint32_t& r1,
                                       uint32_t& r2, uint32_t& r3, uint32_t addr)
{
    asm volatile("ldmatrix.sync.aligned.m8n8.x4.shared.b16 {%0,%1,%2,%3}, [%4];"
                 : "=r"(r0), "=r"(r1), "=r"(r2), "=r"(r3) : "r"(addr));
}

#define CP_ASYNC16(dst, src) \
    asm volatile("cp.async.cg.shared.global [%0], [%1], 16;" :: "r"(dst), "l"(src))
#define CP_COMMIT() asm volatile("cp.async.commit_group;" ::: "memory")
#define CP_WAIT(n)  asm volatile("cp.async.wait_group %0;" :: "n"(n) : "memory")

__device__ __forceinline__ void split2(float a0, float a1, uint32_t& hi, uint32_t& lo) {
    __nv_bfloat162 h = __float22bfloat162_rn(make_float2(a0, a1));
    float2 hf = __bfloat1622float2(h);
    __nv_bfloat162 l = __float22bfloat162_rn(make_float2(a0 - hf.x, a1 - hf.y));
    hi = *reinterpret_cast<uint32_t*>(&h);
    lo = *reinterpret_cast<uint32_t*>(&l);
}

// ---------------------------------------------------------------------------
// Kernel 0: pre-split W into bf16 hi/lo, layout [w][n][k]
// ---------------------------------------------------------------------------
__global__ __launch_bounds__(256) void prep_w(
    const float* __restrict__ wq, const float* __restrict__ wk,
    const float* __restrict__ wv)
{
    int u = blockIdx.x * 256 + threadIdx.x;
    int w = u >> 16;
    int rem = u & 65535;
    int n = rem >> 9;
    int kp = (rem & 511) * 2;
    const float* W = (w == 0) ? wq : (w == 1) ? wk : wv;
    float w0 = W[(size_t)kp * HEAD + n];
    float w1 = W[(size_t)(kp + 1) * HEAD + n];
    uint32_t hi, lo;
    split2(w0, w1, hi, lo);
    size_t off = ((size_t)w * 128 + n) * 1024 + kp;
    *(uint32_t*)&g_w_hi[off] = hi;
    *(uint32_t*)&g_w_lo[off] = lo;
}

// ---------------------------------------------------------------------------
// Kernel 1: projection GEMM  C[M,128] = A[M,1024] @ W[1024,128]
// Pipelined as round 6; MMA issue reordered: each product phase hits 8
// distinct accumulators back-to-back (RAW distance 8).
// ---------------------------------------------------------------------------
#define PKPAD 72
#define PABUF (128 * PKPAD * 2)
#define PSM_TOTAL (8 * PABUF)       // 147456

__device__ __forceinline__ void warp_gemm_proj(float acc[4][4][4],
    uint32_t sAhi, uint32_t sAlo, uint32_t sWhi, uint32_t sWlo,
    uint32_t a_lane, uint32_t b_lane)
{
#pragma unroll
    for (int ks = 0; ks < 4; ks++) {
        const uint32_t kso = (uint32_t)(ks * 16) * 2;
        uint32_t ah[4][4], al[4][4];
#pragma unroll
        for (int mt = 0; mt < 4; mt++) {
            const uint32_t ao = a_lane + (uint32_t)(mt * 16 * PKPAD) * 2 + kso;
            ldm_x4(ah[mt][0], ah[mt][1], ah[mt][2], ah[mt][3], sAhi + ao);
            ldm_x4(al[mt][0], al[mt][1], al[mt][2], al[mt][3], sAlo + ao);
        }
#pragma unroll
        for (int np = 0; np < 2; np++) {
            const uint32_t bo = b_lane + (uint32_t)(np * 16 * PKPAD) * 2 + kso;
            uint32_t bh[4], bl[4];
            ldm_x4(bh[0], bh[1], bh[2], bh[3], sWhi + bo);
            ldm_x4(bl[0], bl[1], bl[2], bl[3], sWlo + bo);
            // phase 1: Ahi x Whi — 8 distinct accumulators
#pragma unroll
            for (int mt = 0; mt < 4; mt++) {
                mma16816(acc[mt][2*np],   ah[mt][0], ah[mt][1], ah[mt][2], ah[mt][3], bh[0], bh[1]);
                mma16816(acc[mt][2*np+1], ah[mt][0], ah[mt][1], ah[mt][2], ah[mt][3], bh[2], bh[3]);
            }
            // phase 2: Alo x Whi
#pragma unroll
            for (int mt = 0; mt < 4; mt++) {
                mma16816(acc[mt][2*np],   al[mt][0], al[mt][1], al[mt][2], al[mt][3], bh[0], bh[1]);
                mma16816(acc[mt][2*np+1], al[mt][0], al[mt][1], al[mt][2], al[mt][3], bh[2], bh[3]);
            }
            // phase 3: Ahi x Wlo
#pragma unroll
            for (int mt = 0; mt < 4; mt++) {
                mma16816(acc[mt][2*np],   ah[mt][0], ah[mt][1], ah[mt][2], ah[mt][3], bl[0], bl[1]);
                mma16816(acc[mt][2*np+1], ah[mt][0], ah[mt][1], ah[mt][2], ah[mt][3], bl[2], bl[3]);
            }
        }
    }
}

__global__ __launch_bounds__(256) void proj_tc(
    const float* __restrict__ in_key,
    const float* __restrict__ in_query,
    const float* __restrict__ in_value)
{
    extern __shared__ __align__(16) char psm[];
    const uint32_t sb = smem_u32(psm);

    const float* A;
    const int p = blockIdx.y;
    if (p == 0)      A = in_query;
    else if (p == 1) A = in_key;
    else             A = in_value;

    const int tid  = threadIdx.x;
    const int wid  = tid >> 5, lane = tid & 31;
    const int g    = lane >> 2, t = lane & 3;
    const int mbase = (wid & 1) * 64;
    const int nbase = (wid >> 1) * 32;
    const int tile = blockIdx.x;
    const int rowBase = tile * 128;

    const uint32_t a_lane = ((mbase + (lane & 15)) * PKPAD + (lane >> 4) * 8) * 2;
    const uint32_t b_lane = ((nbase + (lane & 7) + ((lane >> 4) << 3)) * PKPAD
                             + ((lane >> 3) & 1) * 8) * 2;

    const int aRow0 = tid >> 4;
    const int aC4   = (tid & 15) * 4;

    float acc[4][4][4];
#pragma unroll
    for (int i = 0; i < 4; i++)
#pragma unroll
        for (int j = 0; j < 4; j++)
#pragma unroll
            for (int q = 0; q < 4; q++) acc[i][j][q] = 0.0f;

    const __nv_bfloat16* wsrc_hi = g_w_hi + (size_t)p * 128 * 1024;
    const __nv_bfloat16* wsrc_lo = g_w_lo + (size_t)p * 128 * 1024;

    auto cpa_w = [&](int kb, int s) {
        uint32_t dhi = sb + (4 + 2 * s) * PABUF;
        uint32_t dlo = dhi + PABUF;
#pragma unroll
        for (int it = 0; it < 4; it++) {
            int u = tid + it * 256;
            int row = u >> 3, c = u & 7;
            uint32_t doff = (uint32_t)(row * PKPAD + c * 8) * 2;
            size_t soff = (size_t)row * 1024 + kb * 64 + c * 8;
            CP_ASYNC16(dhi + doff, (const char*)(wsrc_hi + soff));
            CP_ASYNC16(dlo + doff, (const char*)(wsrc_lo + soff));
        }
        CP_COMMIT();
    };

    auto conv_a = [&](const float4* areg, int s) {
        const uint32_t dhi = sb + 2 * s * PABUF;
        const uint32_t dlo = dhi + PABUF;
#pragma unroll
        for (int it = 0; it < 8; it++) {
            uint32_t h0, l0, h1, l1;
            split2(areg[it].x, areg[it].y, h0, l0);
            split2(areg[it].z, areg[it].w, h1, l1);
            uint32_t doff = (uint32_t)((aRow0 + it * 16) * PKPAD + aC4) * 2;
            asm volatile("st.shared.v2.b32 [%0], {%1,%2};" :: "r"(dhi + doff), "r"(h0), "r"(h1));
            asm volatile("st.shared.v2.b32 [%0], {%1,%2};" :: "r"(dlo + doff), "r"(l0), "r"(l1));
        }
    };

    float4 areg[8];
#pragma unroll
    for (int it = 0; it < 8; it++)
        areg[it] = *(const float4*)&A[(size_t)(rowBase + aRow0 + it * 16) * EMB + aC4];
    conv_a(areg, 0);
#pragma unroll
    for (int it = 0; it < 8; it++)
        areg[it] = *(const float4*)&A[(size_t)(rowBase + aRow0 + it * 16) * EMB + 64 + aC4];
    cpa_w(0, 0);

    for (int kb = 0; kb < 16; kb++) {
        CP_WAIT(0);
        __syncthreads();

        if (kb < 15) {
            cpa_w(kb + 1, (kb + 1) & 1);
            conv_a(areg, (kb + 1) & 1);
        }
        if (kb < 14) {
            const int k0n = (kb + 2) * 64;
#pragma unroll
            for (int it = 0; it < 8; it++)
                areg[it] = *(const float4*)&A[(size_t)(rowBase + aRow0 + it * 16) * EMB + k0n + aC4];
        }

        const uint32_t sAhi = sb + 2 * (kb & 1) * PABUF;
        const uint32_t sWhi = sb + (4 + 2 * (kb & 1)) * PABUF;
        warp_gemm_proj(acc, sAhi, sAhi + PABUF, sWhi, sWhi + PABUF, a_lane, b_lane);
    }

    __nv_bfloat16 *dhi, *dlo;
    if (p == 0)      { dhi = g_q_hi; dlo = g_q_lo; }
    else if (p == 1) { dhi = g_k_hi; dlo = g_k_lo; }
    else             { dhi = g_v_hi; dlo = g_v_lo; }
    const size_t base = (size_t)tile * TILE_ELE;

    if (p != 2) {
#pragma unroll
        for (int mt = 0; mt < 4; mt++)
#pragma unroll
            for (int nt = 0; nt < 4; nt++) {
                int r0 = mbase + mt * 16 + g;
                int c  = nbase + nt * 8 + t * 2;
                uint32_t hi, lo;
                split2(acc[mt][nt][0], acc[mt][nt][1], hi, lo);
                *(uint32_t*)(dhi + base + (size_t)r0 * 128 + c) = hi;
                *(uint32_t*)(dlo + base + (size_t)r0 * 128 + c) = lo;
                split2(acc[mt][nt][2], acc[mt][nt][3], hi, lo);
                *(uint32_t*)(dhi + base + (size_t)(r0 + 8) * 128 + c) = hi;
                *(uint32_t*)(dlo + base + (size_t)(r0 + 8) * 128 + c) = lo;
            }
    } else {
#pragma unroll
        for (int mt = 0; mt < 4; mt++)
#pragma unroll
            for (int nt = 0; nt < 4; nt++)
#pragma unroll
                for (int q = 0; q < 4; q++) {
                    int row = mbase + mt * 16 + g + (q >> 1) * 8;
                    int col = nbase + nt * 8 + t * 2 + (q & 1);
                    float v = acc[mt][nt][q];
                    __nv_bfloat16 h = __float2bfloat16(v);
                    __nv_bfloat16 l = __float2bfloat16(v - __bfloat162float(h));
                    dhi[base + (size_t)col * 128 + row] = h;
                    dlo[base + (size_t)col * 128 + row] = l;
                }
    }
}

// ---------------------------------------------------------------------------
// Kernel 2: fused causal retention. MMA phases hit 8 distinct accumulators.
// ---------------------------------------------------------------------------
#define KPAD 136
#define RB (128 * KPAD * 2)
#define SMR_BYTES (6 * RB)

__device__ __forceinline__ void cpa_tile(uint32_t dst, const __nv_bfloat16* __restrict__ src,
                                         int tid) {
#pragma unroll
    for (int it = 0; it < 8; it++) {
        int u = tid + it * 256;
        int row = u >> 4, c = u & 15;
        CP_ASYNC16(dst + (uint32_t)(row * KPAD + c * 8) * 2, (const char*)src + (size_t)u * 16);
    }
}

__global__ __launch_bounds__(256) void retention_tc(float* __restrict__ out)
{
    extern __shared__ __align__(16) char smraw[];
    const uint32_t sb = smem_u32(smraw);
    const uint32_t sQhi = sb,         sQlo = sb + RB;
    const uint32_t sKhi = sb + 2*RB,  sKlo = sb + 3*RB;
    const uint32_t sVhi = sb + 4*RB,  sVlo = sb + 5*RB;

    const int tid  = threadIdx.x;
    const int wid  = tid >> 5, lane = tid & 31;
    const int g    = lane >> 2, t = lane & 3;

    const int b   = blockIdx.x;
    const int cid = blockIdx.y;
    const int qt  = c_qt[cid];
    const int j0  = c_j0[cid];
    const int j1  = c_j1[cid];
    const bool partial = (j1 != qt + 1);
    const int qtile = b * 16 + qt;

    const uint32_t a_lane = (uint32_t)((16 * wid + (lane & 15)) * KPAD + (lane >> 4) * 8) * 2;
    const uint32_t b_lane = (uint32_t)(((lane & 7) + ((lane >> 4) << 3)) * KPAD
                                       + ((lane >> 3) & 1) * 8) * 2;

    cpa_tile(sQhi, g_q_hi + (size_t)qtile * TILE_ELE, tid);
    cpa_tile(sQlo, g_q_lo + (size_t)qtile * TILE_ELE, tid);
    CP_COMMIT();
    {
        const size_t kt = (size_t)(b * 16 + j0) * TILE_ELE;
        cpa_tile(sKhi, g_k_hi + kt, tid);
        cpa_tile(sKlo, g_k_lo + kt, tid);
        CP_COMMIT();
        cpa_tile(sVhi, g_v_hi + kt, tid);
        cpa_tile(sVlo, g_v_lo + kt, tid);
        CP_COMMIT();
    }
    CP_WAIT(1);
    __syncthreads();

    float oacc[16][4];
#pragma unroll
    for (int i = 0; i < 16; i++)
#pragma unroll
        for (int q = 0; q < 4; q++) oacc[i][q] = 0.0f;

    for (int j = j0; j < j1; j++) {
        // ================= GEMM1: S[16 x 128] = Q K^T =================
        float sacc[16][4];
#pragma unroll
        for (int i = 0; i < 16; i++)
#pragma unroll
            for (int q = 0; q < 4; q++) sacc[i][q] = 0.0f;

#pragma unroll 2
        for (int ks = 0; ks < 8; ks++) {
            const uint32_t kso = (uint32_t)(ks * 16) * 2;
            uint32_t ah[4], al[4];
            ldm_x4(ah[0], ah[1], ah[2], ah[3], sQhi + a_lane + kso);
            ldm_x4(al[0], al[1], al[2], al[3], sQlo + a_lane + kso);
#pragma unroll
            for (int nbg = 0; nbg < 2; nbg++) {
                uint32_t bh[4][4], bl[4][4];
#pragma unroll
                for (int i = 0; i < 4; i++) {
                    const uint32_t boff = b_lane
                        + (uint32_t)((nbg * 4 + i) * 16 * KPAD) * 2 + kso;
                    ldm_x4(bh[i][0], bh[i][1], bh[i][2], bh[i][3], sKhi + boff);
                    ldm_x4(bl[i][0], bl[i][1], bl[i][2], bl[i][3], sKlo + boff);
                }
                // phase 1: Qhi x Khi — 8 distinct accumulators
#pragma unroll
                for (int i = 0; i < 4; i++) {
                    mma16816(sacc[8*nbg+2*i],   ah[0], ah[1], ah[2], ah[3], bh[i][0], bh[i][1]);
                    mma16816(sacc[8*nbg+2*i+1], ah[0], ah[1], ah[2], ah[3], bh[i][2], bh[i][3]);
                }
                // phase 2: Qlo x Khi
#pragma unroll
                for (int i = 0; i < 4; i++) {
                    mma16816(sacc[8*nbg+2*i],   al[0], al[1], al[2], al[3], bh[i][0], bh[i][1]);
                    mma16816(sacc[8*nbg+2*i+1], al[0], al[1], al[2], al[3], bh[i][2], bh[i][3]);
                }
                // phase 3: Qhi x Klo
#pragma unroll
                for (int i = 0; i < 4; i++) {
                    mma16816(sacc[8*nbg+2*i],   ah[0], ah[1], ah[2], ah[3], bl[i][0], bl[i][1]);
                    mma16816(sacc[8*nbg+2*i+1], ah[0], ah[1], ah[2], ah[3], bl[i][2], bl[i][3]);
                }
            }
        }

        if (j == qt) {
            const int r0 = 16 * wid + g;
#pragma unroll
            for (int nt = 0; nt < 16; nt++) {
                const int c0 = nt * 8 + t * 2;
                if (c0     > r0)     sacc[nt][0] = 0.0f;
                if (c0 + 1 > r0)     sacc[nt][1] = 0.0f;
                if (c0     > r0 + 8) sacc[nt][2] = 0.0f;
                if (c0 + 1 > r0 + 8) sacc[nt][3] = 0.0f;
            }
        }

        __syncthreads();
        if (j + 1 < j1) {
            const size_t kt = (size_t)(b * 16 + j + 1) * TILE_ELE;
            cpa_tile(sKhi, g_k_hi + kt, tid);
            cpa_tile(sKlo, g_k_lo + kt, tid);
        }
        CP_COMMIT();
        CP_WAIT(1);
        __syncthreads();

        // ================= GEMM2: O += S V (A from registers) =================
#pragma unroll 2
        for (int ks = 0; ks < 8; ks++) {
            uint32_t sh[4], sl[4];
            split2(sacc[2*ks][0],   sacc[2*ks][1],   sh[0], sl[0]);
            split2(sacc[2*ks][2],   sacc[2*ks][3],   sh[1], sl[1]);
            split2(sacc[2*ks+1][0], sacc[2*ks+1][1], sh[2], sl[2]);
            split2(sacc[2*ks+1][2], sacc[2*ks+1][3], sh[3], sl[3]);
            const uint32_t kso = (uint32_t)(ks * 16) * 2;
#pragma unroll
            for (int hbg = 0; hbg < 2; hbg++) {
                uint32_t vh[4][4], vl[4][4];
#pragma unroll
                for (int i = 0; i < 4; i++) {
                    const uint32_t boff = b_lane
                        + (uint32_t)((hbg * 4 + i) * 16 * KPAD) * 2 + kso;
                    ldm_x4(vh[i][0], vh[i][1], vh[i][2], vh[i][3], sVhi + boff);
                    ldm_x4(vl[i][0], vl[i][1], vl[i][2], vl[i][3], sVlo + boff);
                }
                // phase 1: Shi x Vhi
#pragma unroll
                for (int i = 0; i < 4; i++) {
                    mma16816(oacc[8*hbg+2*i],   sh[0], sh[1], sh[2], sh[3], vh[i][0], vh[i][1]);
                    mma16816(oacc[8*hbg+2*i+1], sh[0], sh[1], sh[2], sh[3], vh[i][2], vh[i][3]);
                }
                // phase 2: Slo x Vhi
#pragma unroll
                for (int i = 0; i < 4; i++) {
                    mma16816(oacc[8*hbg+2*i],   sl[0], sl[1], sl[2], sl[3], vh[i][0], vh[i][1]);
                    mma16816(oacc[8*hbg+2*i+1], sl[0], sl[1], sl[2], sl[3], vh[i][2], vh[i][3]);
                }
                // phase 3: Shi x Vlo
#pragma unroll
                for (int i = 0; i < 4; i++) {
                    mma16816(oacc[8*hbg+2*i],   sh[0], sh[1], sh[2], sh[3], vl[i][0], vl[i][1]);
                    mma16816(oacc[8*hbg+2*i+1], sh[0], sh[1], sh[2], sh[3], vl[i][2], vl[i][3]);
                }
            }
        }

        __syncthreads();
        if (j + 1 < j1) {
            const size_t kt = (size_t)(b * 16 + j + 1) * TILE_ELE;
            cpa_tile(sVhi, g_v_hi + kt, tid);
            cpa_tile(sVlo, g_v_lo + kt, tid);
        }
        CP_COMMIT();
        CP_WAIT(1);
        __syncthreads();
    }

    const int r0 = 16 * wid + g;
    if (!partial) {
        const size_t rowbase = (size_t)b * SEQ + (size_t)qt * 128;
#pragma unroll
        for (int ht = 0; ht < 16; ht++) {
            int c = ht * 8 + t * 2;
            *(float2*)&out[(rowbase + r0) * HEAD + c]     = make_float2(oacc[ht][0], oacc[ht][1]);
            *(float2*)&out[(rowbase + r0 + 8) * HEAD + c] = make_float2(oacc[ht][2], oacc[ht][3]);
        }
    } else {
        float* dst = g_opart + (size_t)(b * 8 + (qt - 8)) * TILE_ELE;
#pragma unroll
        for (int ht = 0; ht < 16; ht++) {
            int c = ht * 8 + t * 2;
            *(float2*)&dst[(size_t)r0 * HEAD + c]       = make_float2(oacc[ht][0], oacc[ht][1]);
            *(float2*)&dst[(size_t)(r0 + 8) * HEAD + c] = make_float2(oacc[ht][2], oacc[ht][3]);
        }
    }
}

// ---------------------------------------------------------------------------
// Kernel 3: add partial O chunks into out (qt >= 8 only).
// ---------------------------------------------------------------------------
__global__ __launch_bounds__(256) void reduce_partials(float* __restrict__ out)
{
    int gid = blockIdx.x * 256 + threadIdx.x;
    int tile = gid >> 12;
    int w = gid & 4095;
    int b = tile >> 3, qti = tile & 7;
    float4* o = (float4*)(out + ((size_t)b * SEQ + (size_t)(qti + 8) * 128) * HEAD) + w;
    const float4* p = (const float4*)(g_opart + (size_t)tile * TILE_ELE) + w;
    float4 ov = *o, pv = *p;
    ov.x += pv.x; ov.y += pv.y; ov.z += pv.z; ov.w += pv.w;
    *o = ov;
}

// ---------------------------------------------------------------------------
// Launch
// ---------------------------------------------------------------------------
extern "C" void kernel_launch(void* const* d_in, const int* in_sizes, int n_in,
                              void* d_out, int out_size)
{
    const float* key   = (const float*)d_in[0];
    const float* query = (const float*)d_in[1];
    const float* value = (const float*)d_in[2];
    const float* w_q   = (const float*)d_in[3];
    const float* w_k   = (const float*)d_in[4];
    const float* w_v   = (const float*)d_in[5];
    float* out = (float*)d_out;

    prep_w<<<768, 256>>>(w_q, w_k, w_v);

    cudaFuncSetAttribute(proj_tc,
                         cudaFuncAttributeMaxDynamicSharedMemorySize, PSM_TOTAL);
    dim3 g1(NTILES, 3);
    proj_tc<<<g1, 256, PSM_TOTAL>>>(key, query, value);

    cudaFuncSetAttribute(retention_tc,
                         cudaFuncAttributeMaxDynamicSharedMemorySize, SMR_BYTES);
    dim3 g2(BATCH, 24);
    retention_tc<<<g2, 256, SMR_BYTES>>>(out);

    reduce_partials<<<1024, 256>>>(out);
}

// round 8
// speedup vs baseline: 1.2931x; 1.2931x over previous
#include <cuda_runtime.h>
#include <cuda_bf16.h>
#include <cstdint>

// Problem dims
#define BATCH 8
#define SEQ   2048
#define EMB   1024
#define HEAD  128
#define MROWS (BATCH * SEQ)     // 16384
#define NTILES (MROWS / 128)    // 128
#define TILE_ELE (128 * 128)

// Pre-split bf16 projected tensors, row-major per 128x128 tile.
// Q tiles: [m][h];  K tiles: [n][h];  V tiles: TRANSPOSED [h][n].
__device__ __nv_bfloat16 g_q_hi[NTILES * TILE_ELE];
__device__ __nv_bfloat16 g_q_lo[NTILES * TILE_ELE];
__device__ __nv_bfloat16 g_k_hi[NTILES * TILE_ELE];
__device__ __nv_bfloat16 g_k_lo[NTILES * TILE_ELE];
__device__ __nv_bfloat16 g_v_hi[NTILES * TILE_ELE];
__device__ __nv_bfloat16 g_v_lo[NTILES * TILE_ELE];

// Pre-split weights: [w][n][k], k contiguous
__device__ __nv_bfloat16 g_w_hi[3 * 128 * 1024];
__device__ __nv_bfloat16 g_w_lo[3 * 128 * 1024];

// Partial O accumulators: 15 slots per batch
#define NSLOTS 15
__device__ float g_opart[BATCH * NSLOTS * TILE_ELE];

// Chunk schedule: 31 chunks per batch, max 6 iters, longest first.
// slot = -1 means the chunk contains the diagonal and writes out directly.
#define NCHUNK 31
__constant__ int c_qt[NCHUNK] =
    {15,11,11,10,15,15,14,14,14,13,13,12,10, 9, 9, 8, 4,13,12,12, 8, 7, 7, 6, 3, 6, 5, 5, 2, 1, 0};
__constant__ int c_j0[NCHUNK] =
    { 0, 0, 6, 0, 6,11, 0, 5,10, 0, 5, 0, 6, 0, 5, 0, 0,10, 5, 9, 5, 0, 4, 0, 0, 4, 0, 3, 0, 0, 0};
__constant__ int c_j1[NCHUNK] =
    { 6, 6,12, 6,11,16, 5,10,15, 5,10, 5,11, 5,10, 5, 5,14, 9,13, 9, 4, 8, 4, 4, 7, 3, 6, 3, 2, 1};
__constant__ int c_slot[NCHUNK] =
    { 0, 8,-1, 9, 1,-1, 2, 3,-1, 4, 5, 6,-1,10,-1,11,-1,-1, 7,-1,-1,12,-1,13,-1,-1,14,-1,-1,-1,-1};

// Reduce table: qts that have partial slots
__constant__ int r_qt[11] = {15,14,13,12,11,10, 9, 8, 7, 6, 5};
__constant__ int r_s0[11] = { 0, 2, 4, 6, 8, 9,10,11,12,13,14};
__constant__ int r_ns[11] = { 2, 2, 2, 2, 1, 1, 1, 1, 1, 1, 1};

// ---------------------------------------------------------------------------
// PTX helpers (family-generic)
// ---------------------------------------------------------------------------
__device__ __forceinline__ uint32_t smem_u32(const void* p) {
    uint32_t a;
    asm("{ .reg .u64 t; cvta.to.shared.u64 t, %1; cvt.u32.u64 %0, t; }"
        : "=r"(a) : "l"(p));
    return a;
}

__device__ __forceinline__ void mma16816(float* c,
    uint32_t a0, uint32_t a1, uint32_t a2, uint32_t a3,
    uint32_t b0, uint32_t b1)
{
    asm volatile(
        "mma.sync.aligned.m16n8k16.row.col.f32.bf16.bf16.f32 "
        "{%0,%1,%2,%3}, {%4,%5,%6,%7}, {%8,%9}, {%0,%1,%2,%3};"
        : "+f"(c[0]), "+f"(c[1]), "+f"(c[2]), "+f"(c[3])
        : "r"(a0), "r"(a1), "r"(a2), "r"(a3), "r"(b0), "r"(b1));
}

__device__ __forceinline__ void ldm_x4(uint32_t& r0, uint32_t& r1,
                                       uint32_t& r2, uint32_t& r3, uint32_t addr)
{
    asm volatile("ldmatrix.sync.aligned.m8n8.x4.shared.b16 {%0,%1,%2,%3}, [%4];"
                 : "=r"(r0), "=r"(r1), "=r"(r2), "=r"(r3) : "r"(addr));
}

#define CP_ASYNC16(dst, src) \
    asm volatile("cp.async.cg.shared.global [%0], [%1], 16;" :: "r"(dst), "l"(src))
#define CP_COMMIT() asm volatile("cp.async.commit_group;" ::: "memory")
#define CP_WAIT(n)  asm volatile("cp.async.wait_group %0;" :: "n"(n) : "memory")

__device__ __forceinline__ void split2(float a0, float a1, uint32_t& hi, uint32_t& lo) {
    __nv_bfloat162 h = __float22bfloat162_rn(make_float2(a0, a1));
    float2 hf = __bfloat1622float2(h);
    __nv_bfloat162 l = __float22bfloat162_rn(make_float2(a0 - hf.x, a1 - hf.y));
    hi = *reinterpret_cast<uint32_t*>(&h);
    lo = *reinterpret_cast<uint32_t*>(&l);
}

// ---------------------------------------------------------------------------
// Kernel 0: pre-split W into bf16 hi/lo, layout [w][n][k]
// ---------------------------------------------------------------------------
__global__ __launch_bounds__(256) void prep_w(
    const float* __restrict__ wq, const float* __restrict__ wk,
    const float* __restrict__ wv)
{
    int u = blockIdx.x * 256 + threadIdx.x;
    int w = u >> 16;
    int rem = u & 65535;
    int n = rem >> 9;
    int kp = (rem & 511) * 2;
    const float* W = (w == 0) ? wq : (w == 1) ? wk : wv;
    float w0 = W[(size_t)kp * HEAD + n];
    float w1 = W[(size_t)(kp + 1) * HEAD + n];
    uint32_t hi, lo;
    split2(w0, w1, hi, lo);
    size_t off = ((size_t)w * 128 + n) * 1024 + kp;
    *(uint32_t*)&g_w_hi[off] = hi;
    *(uint32_t*)&g_w_lo[off] = lo;
}

// ---------------------------------------------------------------------------
// Kernel 1: projection GEMM (round-6 proven version, unchanged)
// ---------------------------------------------------------------------------
#define PKPAD 72
#define PABUF (128 * PKPAD * 2)
#define PSM_TOTAL (8 * PABUF)       // 147456

__device__ __forceinline__ void warp_gemm_proj(float acc[4][4][4],
    uint32_t sAhi, uint32_t sAlo, uint32_t sWhi, uint32_t sWlo,
    uint32_t a_lane, uint32_t b_lane)
{
#pragma unroll
    for (int ks = 0; ks < 4; ks++) {
        const uint32_t kso = (uint32_t)(ks * 16) * 2;
        uint32_t ah[4][4], al[4][4];
#pragma unroll
        for (int mt = 0; mt < 4; mt++) {
            const uint32_t ao = a_lane + (uint32_t)(mt * 16 * PKPAD) * 2 + kso;
            ldm_x4(ah[mt][0], ah[mt][1], ah[mt][2], ah[mt][3], sAhi + ao);
            ldm_x4(al[mt][0], al[mt][1], al[mt][2], al[mt][3], sAlo + ao);
        }
#pragma unroll
        for (int np = 0; np < 2; np++) {
            const uint32_t bo = b_lane + (uint32_t)(np * 16 * PKPAD) * 2 + kso;
            uint32_t bh[4], bl[4];
            ldm_x4(bh[0], bh[1], bh[2], bh[3], sWhi + bo);
            ldm_x4(bl[0], bl[1], bl[2], bl[3], sWlo + bo);
#pragma unroll
            for (int mt = 0; mt < 4; mt++) {
                mma16816(acc[mt][2*np],   ah[mt][0], ah[mt][1], ah[mt][2], ah[mt][3], bh[0], bh[1]);
                mma16816(acc[mt][2*np+1], ah[mt][0], ah[mt][1], ah[mt][2], ah[mt][3], bh[2], bh[3]);
                mma16816(acc[mt][2*np],   ah[mt][0], ah[mt][1], ah[mt][2], ah[mt][3], bl[0], bl[1]);
                mma16816(acc[mt][2*np+1], ah[mt][0], ah[mt][1], ah[mt][2], ah[mt][3], bl[2], bl[3]);
                mma16816(acc[mt][2*np],   al[mt][0], al[mt][1], al[mt][2], al[mt][3], bh[0], bh[1]);
                mma16816(acc[mt][2*np+1], al[mt][0], al[mt][1], al[mt][2], al[mt][3], bh[2], bh[3]);
            }
        }
    }
}

__global__ __launch_bounds__(256) void proj_tc(
    const float* __restrict__ in_key,
    const float* __restrict__ in_query,
    const float* __restrict__ in_value)
{
    extern __shared__ __align__(16) char psm[];
    const uint32_t sb = smem_u32(psm);

    const float* A;
    const int p = blockIdx.y;
    if (p == 0)      A = in_query;
    else if (p == 1) A = in_key;
    else             A = in_value;

    const int tid  = threadIdx.x;
    const int wid  = tid >> 5, lane = tid & 31;
    const int g    = lane >> 2, t = lane & 3;
    const int mbase = (wid & 1) * 64;
    const int nbase = (wid >> 1) * 32;
    const int tile = blockIdx.x;
    const int rowBase = tile * 128;

    const uint32_t a_lane = ((mbase + (lane & 15)) * PKPAD + (lane >> 4) * 8) * 2;
    const uint32_t b_lane = ((nbase + (lane & 7) + ((lane >> 4) << 3)) * PKPAD
                             + ((lane >> 3) & 1) * 8) * 2;

    const int aRow0 = tid >> 4;
    const int aC4   = (tid & 15) * 4;

    float acc[4][4][4];
#pragma unroll
    for (int i = 0; i < 4; i++)
#pragma unroll
        for (int j = 0; j < 4; j++)
#pragma unroll
            for (int q = 0; q < 4; q++) acc[i][j][q] = 0.0f;

    const __nv_bfloat16* wsrc_hi = g_w_hi + (size_t)p * 128 * 1024;
    const __nv_bfloat16* wsrc_lo = g_w_lo + (size_t)p * 128 * 1024;

    auto cpa_w = [&](int kb, int s) {
        uint32_t dhi = sb + (4 + 2 * s) * PABUF;
        uint32_t dlo = dhi + PABUF;
#pragma unroll
        for (int it = 0; it < 4; it++) {
            int u = tid + it * 256;
            int row = u >> 3, c = u & 7;
            uint32_t doff = (uint32_t)(row * PKPAD + c * 8) * 2;
            size_t soff = (size_t)row * 1024 + kb * 64 + c * 8;
            CP_ASYNC16(dhi + doff, (const char*)(wsrc_hi + soff));
            CP_ASYNC16(dlo + doff, (const char*)(wsrc_lo + soff));
        }
        CP_COMMIT();
    };

    auto conv_a = [&](const float4* areg, int s) {
        const uint32_t dhi = sb + 2 * s * PABUF;
        const uint32_t dlo = dhi + PABUF;
#pragma unroll
        for (int it = 0; it < 8; it++) {
            uint32_t h0, l0, h1, l1;
            split2(areg[it].x, areg[it].y, h0, l0);
            split2(areg[it].z, areg[it].w, h1, l1);
            uint32_t doff = (uint32_t)((aRow0 + it * 16) * PKPAD + aC4) * 2;
            asm volatile("st.shared.v2.b32 [%0], {%1,%2};" :: "r"(dhi + doff), "r"(h0), "r"(h1));
            asm volatile("st.shared.v2.b32 [%0], {%1,%2};" :: "r"(dlo + doff), "r"(l0), "r"(l1));
        }
    };

    float4 areg[8];
#pragma unroll
    for (int it = 0; it < 8; it++)
        areg[it] = *(const float4*)&A[(size_t)(rowBase + aRow0 + it * 16) * EMB + aC4];
    conv_a(areg, 0);
#pragma unroll
    for (int it = 0; it < 8; it++)
        areg[it] = *(const float4*)&A[(size_t)(rowBase + aRow0 + it * 16) * EMB + 64 + aC4];
    cpa_w(0, 0);

    for (int kb = 0; kb < 16; kb++) {
        CP_WAIT(0);
        __syncthreads();

        if (kb < 15) {
            cpa_w(kb + 1, (kb + 1) & 1);
            conv_a(areg, (kb + 1) & 1);
        }
        if (kb < 14) {
            const int k0n = (kb + 2) * 64;
#pragma unroll
            for (int it = 0; it < 8; it++)
                areg[it] = *(const float4*)&A[(size_t)(rowBase + aRow0 + it * 16) * EMB + k0n + aC4];
        }

        const uint32_t sAhi = sb + 2 * (kb & 1) * PABUF;
        const uint32_t sWhi = sb + (4 + 2 * (kb & 1)) * PABUF;
        warp_gemm_proj(acc, sAhi, sAhi + PABUF, sWhi, sWhi + PABUF, a_lane, b_lane);
    }

    __nv_bfloat16 *dhi, *dlo;
    if (p == 0)      { dhi = g_q_hi; dlo = g_q_lo; }
    else if (p == 1) { dhi = g_k_hi; dlo = g_k_lo; }
    else             { dhi = g_v_hi; dlo = g_v_lo; }
    const size_t base = (size_t)tile * TILE_ELE;

    if (p != 2) {
#pragma unroll
        for (int mt = 0; mt < 4; mt++)
#pragma unroll
            for (int nt = 0; nt < 4; nt++) {
                int r0 = mbase + mt * 16 + g;
                int c  = nbase + nt * 8 + t * 2;
                uint32_t hi, lo;
                split2(acc[mt][nt][0], acc[mt][nt][1], hi, lo);
                *(uint32_t*)(dhi + base + (size_t)r0 * 128 + c) = hi;
                *(uint32_t*)(dlo + base + (size_t)r0 * 128 + c) = lo;
                split2(acc[mt][nt][2], acc[mt][nt][3], hi, lo);
                *(uint32_t*)(dhi + base + (size_t)(r0 + 8) * 128 + c) = hi;
                *(uint32_t*)(dlo + base + (size_t)(r0 + 8) * 128 + c) = lo;
            }
    } else {
#pragma unroll
        for (int mt = 0; mt < 4; mt++)
#pragma unroll
            for (int nt = 0; nt < 4; nt++)
#pragma unroll
                for (int q = 0; q < 4; q++) {
                    int row = mbase + mt * 16 + g + (q >> 1) * 8;
                    int col = nbase + nt * 8 + t * 2 + (q & 1);
                    float v = acc[mt][nt][q];
                    __nv_bfloat16 h = __float2bfloat16(v);
                    __nv_bfloat16 l = __float2bfloat16(v - __bfloat162float(h));
                    dhi[base + (size_t)col * 128 + row] = h;
                    dlo[base + (size_t)col * 128 + row] = l;
                }
    }
}

// ---------------------------------------------------------------------------
// Kernel 2: fused causal retention (round-6 proven inner loops, new schedule)
// ---------------------------------------------------------------------------
#define KPAD 136
#define RB (128 * KPAD * 2)
#define SMR_BYTES (6 * RB)

__device__ __forceinline__ void cpa_tile(uint32_t dst, const __nv_bfloat16* __restrict__ src,
                                         int tid) {
#pragma unroll
    for (int it = 0; it < 8; it++) {
        int u = tid + it * 256;
        int row = u >> 4, c = u & 15;
        CP_ASYNC16(dst + (uint32_t)(row * KPAD + c * 8) * 2, (const char*)src + (size_t)u * 16);
    }
}

__global__ __launch_bounds__(256) void retention_tc(float* __restrict__ out)
{
    extern __shared__ __align__(16) char smraw[];
    const uint32_t sb = smem_u32(smraw);
    const uint32_t sQhi = sb,         sQlo = sb + RB;
    const uint32_t sKhi = sb + 2*RB,  sKlo = sb + 3*RB;
    const uint32_t sVhi = sb + 4*RB,  sVlo = sb + 5*RB;

    const int tid  = threadIdx.x;
    const int wid  = tid >> 5, lane = tid & 31;
    const int g    = lane >> 2, t = lane & 3;

    const int b    = blockIdx.x;
    const int cid  = blockIdx.y;
    const int qt   = c_qt[cid];
    const int j0   = c_j0[cid];
    const int j1   = c_j1[cid];
    const int slot = c_slot[cid];
    const int qtile = b * 16 + qt;

    const uint32_t a_lane = (uint32_t)((16 * wid + (lane & 15)) * KPAD + (lane >> 4) * 8) * 2;
    const uint32_t b_lane = (uint32_t)(((lane & 7) + ((lane >> 4) << 3)) * KPAD
                                       + ((lane >> 3) & 1) * 8) * 2;

    cpa_tile(sQhi, g_q_hi + (size_t)qtile * TILE_ELE, tid);
    cpa_tile(sQlo, g_q_lo + (size_t)qtile * TILE_ELE, tid);
    CP_COMMIT();
    {
        const size_t kt = (size_t)(b * 16 + j0) * TILE_ELE;
        cpa_tile(sKhi, g_k_hi + kt, tid);
        cpa_tile(sKlo, g_k_lo + kt, tid);
        CP_COMMIT();
        cpa_tile(sVhi, g_v_hi + kt, tid);
        cpa_tile(sVlo, g_v_lo + kt, tid);
        CP_COMMIT();
    }
    CP_WAIT(1);
    __syncthreads();

    float oacc[16][4];
#pragma unroll
    for (int i = 0; i < 16; i++)
#pragma unroll
        for (int q = 0; q < 4; q++) oacc[i][q] = 0.0f;

    for (int j = j0; j < j1; j++) {
        float sacc[16][4];
#pragma unroll
        for (int i = 0; i < 16; i++)
#pragma unroll
            for (int q = 0; q < 4; q++) sacc[i][q] = 0.0f;

#pragma unroll 2
        for (int ks = 0; ks < 8; ks++) {
            const uint32_t kso = (uint32_t)(ks * 16) * 2;
            uint32_t ah[4], al[4];
            ldm_x4(ah[0], ah[1], ah[2], ah[3], sQhi + a_lane + kso);
            ldm_x4(al[0], al[1], al[2], al[3], sQlo + a_lane + kso);
#pragma unroll
            for (int nb = 0; nb < 8; nb++) {
                const uint32_t boff = b_lane + (uint32_t)(nb * 16 * KPAD) * 2 + kso;
                uint32_t bh[4];
                ldm_x4(bh[0], bh[1], bh[2], bh[3], sKhi + boff);
                mma16816(sacc[2*nb],   ah[0], ah[1], ah[2], ah[3], bh[0], bh[1]);
                mma16816(sacc[2*nb+1], ah[0], ah[1], ah[2], ah[3], bh[2], bh[3]);
                mma16816(sacc[2*nb],   al[0], al[1], al[2], al[3], bh[0], bh[1]);
                mma16816(sacc[2*nb+1], al[0], al[1], al[2], al[3], bh[2], bh[3]);
                ldm_x4(bh[0], bh[1], bh[2], bh[3], sKlo + boff);
                mma16816(sacc[2*nb],   ah[0], ah[1], ah[2], ah[3], bh[0], bh[1]);
                mma16816(sacc[2*nb+1], ah[0], ah[1], ah[2], ah[3], bh[2], bh[3]);
            }
        }

        if (j == qt) {
            const int r0 = 16 * wid + g;
#pragma unroll
            for (int nt = 0; nt < 16; nt++) {
                const int c0 = nt * 8 + t * 2;
                if (c0     > r0)     sacc[nt][0] = 0.0f;
                if (c0 + 1 > r0)     sacc[nt][1] = 0.0f;
                if (c0     > r0 + 8) sacc[nt][2] = 0.0f;
                if (c0 + 1 > r0 + 8) sacc[nt][3] = 0.0f;
            }
        }

        __syncthreads();
        if (j + 1 < j1) {
            const size_t kt = (size_t)(b * 16 + j + 1) * TILE_ELE;
            cpa_tile(sKhi, g_k_hi + kt, tid);
            cpa_tile(sKlo, g_k_lo + kt, tid);
        }
        CP_COMMIT();
        CP_WAIT(1);
        __syncthreads();

#pragma unroll
        for (int ks = 0; ks < 8; ks++) {
            uint32_t sh[4], sl[4];
            split2(sacc[2*ks][0],   sacc[2*ks][1],   sh[0], sl[0]);
            split2(sacc[2*ks][2],   sacc[2*ks][3],   sh[1], sl[1]);
            split2(sacc[2*ks+1][0], sacc[2*ks+1][1], sh[2], sl[2]);
            split2(sacc[2*ks+1][2], sacc[2*ks+1][3], sh[3], sl[3]);
            const uint32_t kso = (uint32_t)(ks * 16) * 2;
#pragma unroll
            for (int hb = 0; hb < 8; hb++) {
                const uint32_t boff = b_lane + (uint32_t)(hb * 16 * KPAD) * 2 + kso;
                uint32_t bh[4];
                ldm_x4(bh[0], bh[1], bh[2], bh[3], sVhi + boff);
                mma16816(oacc[2*hb],   sh[0], sh[1], sh[2], sh[3], bh[0], bh[1]);
                mma16816(oacc[2*hb+1], sh[0], sh[1], sh[2], sh[3], bh[2], bh[3]);
                mma16816(oacc[2*hb],   sl[0], sl[1], sl[2], sl[3], bh[0], bh[1]);
                mma16816(oacc[2*hb+1], sl[0], sl[1], sl[2], sl[3], bh[2], bh[3]);
                ldm_x4(bh[0], bh[1], bh[2], bh[3], sVlo + boff);
                mma16816(oacc[2*hb],   sh[0], sh[1], sh[2], sh[3], bh[0], bh[1]);
                mma16816(oacc[2*hb+1], sh[0], sh[1], sh[2], sh[3], bh[2], bh[3]);
            }
        }

        __syncthreads();
        if (j + 1 < j1) {
            const size_t kt = (size_t)(b * 16 + j + 1) * TILE_ELE;
            cpa_tile(sVhi, g_v_hi + kt, tid);
            cpa_tile(sVlo, g_v_lo + kt, tid);
        }
        CP_COMMIT();
        CP_WAIT(1);
        __syncthreads();
    }

    const int r0 = 16 * wid + g;
    if (slot < 0) {
        const size_t rowbase = (size_t)b * SEQ + (size_t)qt * 128;
#pragma unroll
        for (int ht = 0; ht < 16; ht++) {
            int c = ht * 8 + t * 2;
            *(float2*)&out[(rowbase + r0) * HEAD + c]     = make_float2(oacc[ht][0], oacc[ht][1]);
            *(float2*)&out[(rowbase + r0 + 8) * HEAD + c] = make_float2(oacc[ht][2], oacc[ht][3]);
        }
    } else {
        float* dst = g_opart + (size_t)(b * NSLOTS + slot) * TILE_ELE;
#pragma unroll
        for (int ht = 0; ht < 16; ht++) {
            int c = ht * 8 + t * 2;
            *(float2*)&dst[(size_t)r0 * HEAD + c]       = make_float2(oacc[ht][0], oacc[ht][1]);
            *(float2*)&dst[(size_t)(r0 + 8) * HEAD + c] = make_float2(oacc[ht][2], oacc[ht][3]);
        }
    }
}

// ---------------------------------------------------------------------------
// Kernel 3: add partial slots into out. One block per (batch, partial-qt),
// so no cross-block races on the same output tile.
// ---------------------------------------------------------------------------
__global__ __launch_bounds__(256) void reduce_partials(float* __restrict__ out)
{
    const int b  = blockIdx.x;
    const int qi = blockIdx.y;          // 0..10
    const int qt = r_qt[qi];
    const int s0 = r_s0[qi];
    const int ns = r_ns[qi];

    float4* otile = (float4*)(out + ((size_t)b * SEQ + (size_t)qt * 128) * HEAD);
    const float4* p0 = (const float4*)(g_opart + (size_t)(b * NSLOTS + s0) * TILE_ELE);
    const float4* p1 = (const float4*)(g_opart + (size_t)(b * NSLOTS + s0 + 1) * TILE_ELE);

#pragma unroll
    for (int it = 0; it < 16; it++) {
        int w = threadIdx.x + it * 256;     // 0..4095 float4
        float4 ov = otile[w];
        float4 pv = p0[w];
        ov.x += pv.x; ov.y += pv.y; ov.z += pv.z; ov.w += pv.w;
        if (ns == 2) {
            float4 qv = p1[w];
            ov.x += qv.x; ov.y += qv.y; ov.z += qv.z; ov.w += qv.w;
        }
        otile[w] = ov;
    }
}

// ---------------------------------------------------------------------------
// Launch
// ---------------------------------------------------------------------------
extern "C" void kernel_launch(void* const* d_in, const int* in_sizes, int n_in,
                              void* d_out, int out_size)
{
    const float* key   = (const float*)d_in[0];
    const float* query = (const float*)d_in[1];
    const float* value = (const float*)d_in[2];
    const float* w_q   = (const float*)d_in[3];
    const float* w_k   = (const float*)d_in[4];
    const float* w_v   = (const float*)d_in[5];
    float* out = (float*)d_out;

    prep_w<<<768, 256>>>(w_q, w_k, w_v);

    cudaFuncSetAttribute(proj_tc,
                         cudaFuncAttributeMaxDynamicSharedMemorySize, PSM_TOTAL);
    dim3 g1(NTILES, 3);
    proj_tc<<<g1, 256, PSM_TOTAL>>>(key, query, value);

    cudaFuncSetAttribute(retention_tc,
                         cudaFuncAttributeMaxDynamicSharedMemorySize, SMR_BYTES);
    dim3 g2(BATCH, NCHUNK);
    retention_tc<<<g2, 256, SMR_BYTES>>>(out);

    dim3 g3(BATCH, 11);
    reduce_partials<<<g3, 256>>>(out);
}

// round 9
// speedup vs baseline: 1.7978x; 1.3903x over previous
#include <cuda_runtime.h>
#include <cuda_fp16.h>
#include <cstdint>

// Problem dims
#define BATCH 8
#define SEQ   2048
#define EMB   1024
#define HEAD  128
#define MROWS (BATCH * SEQ)     // 16384
#define NTILES (MROWS / 128)    // 128
#define TILE_ELE (128 * 128)

// fp16 projected tensors, row-major per 128x128 tile.
// Q: hi+lo (split side of GEMM1). K: hi only. V: hi only, TRANSPOSED [h][n].
__device__ __half g_q_hi[NTILES * TILE_ELE];
__device__ __half g_q_lo[NTILES * TILE_ELE];
__device__ __half g_k_hi[NTILES * TILE_ELE];
__device__ __half g_v_hi[NTILES * TILE_ELE];

// Split weights (B side of proj): [w][n][k], k contiguous
__device__ __half g_w_hi[3 * 128 * 1024];
__device__ __half g_w_lo[3 * 128 * 1024];

// Partial O accumulators for split-K chunks (qt >= 8)
__device__ float g_opart[BATCH * 8 * TILE_ELE];

// Chunk schedule (round-6 proven): 24 chunks per batch, longest first.
__constant__ int c_qt[24] = {15,15,14, 7,14,13,13,12, 6,12,11,11,10, 5,10, 9, 9, 8, 4, 8, 3, 2, 1, 0};
__constant__ int c_j0[24] = { 0, 8, 0, 0, 8, 0, 7, 0, 0, 7, 0, 6, 0, 0, 6, 0, 5, 0, 0, 5, 0, 0, 0, 0};
__constant__ int c_j1[24] = { 8,16, 8, 8,15, 7,14, 7, 7,13, 6,12, 6, 6,11, 5,10, 5, 5, 9, 4, 3, 2, 1};

// ---------------------------------------------------------------------------
// PTX helpers (family-generic)
// ---------------------------------------------------------------------------
__device__ __forceinline__ uint32_t smem_u32(const void* p) {
    uint32_t a;
    asm("{ .reg .u64 t; cvta.to.shared.u64 t, %1; cvt.u32.u64 %0, t; }"
        : "=r"(a) : "l"(p));
    return a;
}

__device__ __forceinline__ void mma16816(float* c,
    uint32_t a0, uint32_t a1, uint32_t a2, uint32_t a3,
    uint32_t b0, uint32_t b1)
{
    asm volatile(
        "mma.sync.aligned.m16n8k16.row.col.f32.f16.f16.f32 "
        "{%0,%1,%2,%3}, {%4,%5,%6,%7}, {%8,%9}, {%0,%1,%2,%3};"
        : "+f"(c[0]), "+f"(c[1]), "+f"(c[2]), "+f"(c[3])
        : "r"(a0), "r"(a1), "r"(a2), "r"(a3), "r"(b0), "r"(b1));
}

__device__ __forceinline__ void ldm_x4(uint32_t& r0, uint32_t& r1,
                                       uint32_t& r2, uint32_t& r3, uint32_t addr)
{
    asm volatile("ldmatrix.sync.aligned.m8n8.x4.shared.b16 {%0,%1,%2,%3}, [%4];"
                 : "=r"(r0), "=r"(r1), "=r"(r2), "=r"(r3) : "r"(addr));
}

#define CP_ASYNC16(dst, src) \
    asm volatile("cp.async.cg.shared.global [%0], [%1], 16;" :: "r"(dst), "l"(src))
#define CP_COMMIT() asm volatile("cp.async.commit_group;" ::: "memory")
#define CP_WAIT(n)  asm volatile("cp.async.wait_group %0;" :: "n"(n) : "memory")

// fp16 split: packed hi pair + packed residual pair
__device__ __forceinline__ void split2h(float a0, float a1, uint32_t& hi, uint32_t& lo) {
    __half2 h = __float22half2_rn(make_float2(a0, a1));
    float2 hf = __half22float2(h);
    __half2 l = __float22half2_rn(make_float2(a0 - hf.x, a1 - hf.y));
    hi = *reinterpret_cast<uint32_t*>(&h);
    lo = *reinterpret_cast<uint32_t*>(&l);
}
__device__ __forceinline__ uint32_t cvt2h(float a0, float a1) {
    __half2 h = __float22half2_rn(make_float2(a0, a1));
    return *reinterpret_cast<uint32_t*>(&h);
}

// ---------------------------------------------------------------------------
// Kernel 0: pre-split W into fp16 hi/lo, layout [w][n][k]
// ---------------------------------------------------------------------------
__global__ __launch_bounds__(256) void prep_w(
    const float* __restrict__ wq, const float* __restrict__ wk,
    const float* __restrict__ wv)
{
    int u = blockIdx.x * 256 + threadIdx.x;
    int w = u >> 16;
    int rem = u & 65535;
    int n = rem >> 9;
    int kp = (rem & 511) * 2;
    const float* W = (w == 0) ? wq : (w == 1) ? wk : wv;
    float w0 = W[(size_t)kp * HEAD + n];
    float w1 = W[(size_t)(kp + 1) * HEAD + n];
    uint32_t hi, lo;
    split2h(w0, w1, hi, lo);
    size_t off = ((size_t)w * 128 + n) * 1024 + kp;
    *(uint32_t*)&g_w_hi[off] = hi;
    *(uint32_t*)&g_w_lo[off] = lo;
}

// ---------------------------------------------------------------------------
// Kernel 1: projection GEMM  C = A @ W.  A hi-only (fp16), W hi+lo.
// Round-6 pipeline: A double-buffered via regs+STS, W double-buffered cp.async.
// ---------------------------------------------------------------------------
#define PKPAD 72
#define PABUF (128 * PKPAD * 2)
// smem: A0 0, A1 1, W0h 2, W0l 3, W1h 4, W1l 5
#define PSM_TOTAL (6 * PABUF)       // 110592

__device__ __forceinline__ void warp_gemm_proj(float acc[4][4][4],
    uint32_t sA, uint32_t sWhi, uint32_t sWlo,
    uint32_t a_lane, uint32_t b_lane)
{
#pragma unroll
    for (int ks = 0; ks < 4; ks++) {
        const uint32_t kso = (uint32_t)(ks * 16) * 2;
        uint32_t ah[4][4];
#pragma unroll
        for (int mt = 0; mt < 4; mt++) {
            const uint32_t ao = a_lane + (uint32_t)(mt * 16 * PKPAD) * 2 + kso;
            ldm_x4(ah[mt][0], ah[mt][1], ah[mt][2], ah[mt][3], sA + ao);
        }
#pragma unroll
        for (int np = 0; np < 2; np++) {
            const uint32_t bo = b_lane + (uint32_t)(np * 16 * PKPAD) * 2 + kso;
            uint32_t bh[4], bl[4];
            ldm_x4(bh[0], bh[1], bh[2], bh[3], sWhi + bo);
            ldm_x4(bl[0], bl[1], bl[2], bl[3], sWlo + bo);
#pragma unroll
            for (int mt = 0; mt < 4; mt++) {
                mma16816(acc[mt][2*np],   ah[mt][0], ah[mt][1], ah[mt][2], ah[mt][3], bh[0], bh[1]);
                mma16816(acc[mt][2*np+1], ah[mt][0], ah[mt][1], ah[mt][2], ah[mt][3], bh[2], bh[3]);
                mma16816(acc[mt][2*np],   ah[mt][0], ah[mt][1], ah[mt][2], ah[mt][3], bl[0], bl[1]);
                mma16816(acc[mt][2*np+1], ah[mt][0], ah[mt][1], ah[mt][2], ah[mt][3], bl[2], bl[3]);
            }
        }
    }
}

__global__ __launch_bounds__(256) void proj_tc(
    const float* __restrict__ in_key,
    const float* __restrict__ in_query,
    const float* __restrict__ in_value)
{
    extern __shared__ __align__(16) char psm[];
    const uint32_t sb = smem_u32(psm);

    const float* A;
    const int p = blockIdx.y;
    if (p == 0)      A = in_query;
    else if (p == 1) A = in_key;
    else             A = in_value;

    const int tid  = threadIdx.x;
    const int wid  = tid >> 5, lane = tid & 31;
    const int g    = lane >> 2, t = lane & 3;
    const int mbase = (wid & 1) * 64;
    const int nbase = (wid >> 1) * 32;
    const int tile = blockIdx.x;
    const int rowBase = tile * 128;

    const uint32_t a_lane = ((mbase + (lane & 15)) * PKPAD + (lane >> 4) * 8) * 2;
    const uint32_t b_lane = ((nbase + (lane & 7) + ((lane >> 4) << 3)) * PKPAD
                             + ((lane >> 3) & 1) * 8) * 2;

    const int aRow0 = tid >> 4;
    const int aC4   = (tid & 15) * 4;

    float acc[4][4][4];
#pragma unroll
    for (int i = 0; i < 4; i++)
#pragma unroll
        for (int j = 0; j < 4; j++)
#pragma unroll
            for (int q = 0; q < 4; q++) acc[i][j][q] = 0.0f;

    const __half* wsrc_hi = g_w_hi + (size_t)p * 128 * 1024;
    const __half* wsrc_lo = g_w_lo + (size_t)p * 128 * 1024;

    auto cpa_w = [&](int kb, int s) {
        uint32_t dhi = sb + (2 + 2 * s) * PABUF;
        uint32_t dlo = dhi + PABUF;
#pragma unroll
        for (int it = 0; it < 4; it++) {
            int u = tid + it * 256;
            int row = u >> 3, c = u & 7;
            uint32_t doff = (uint32_t)(row * PKPAD + c * 8) * 2;
            size_t soff = (size_t)row * 1024 + kb * 64 + c * 8;
            CP_ASYNC16(dhi + doff, (const char*)(wsrc_hi + soff));
            CP_ASYNC16(dlo + doff, (const char*)(wsrc_lo + soff));
        }
        CP_COMMIT();
    };

    auto conv_a = [&](const float4* areg, int s) {
        const uint32_t dA = sb + s * PABUF;
#pragma unroll
        for (int it = 0; it < 8; it++) {
            uint32_t h0 = cvt2h(areg[it].x, areg[it].y);
            uint32_t h1 = cvt2h(areg[it].z, areg[it].w);
            uint32_t doff = (uint32_t)((aRow0 + it * 16) * PKPAD + aC4) * 2;
            asm volatile("st.shared.v2.b32 [%0], {%1,%2};" :: "r"(dA + doff), "r"(h0), "r"(h1));
        }
    };

    float4 areg[8];
#pragma unroll
    for (int it = 0; it < 8; it++)
        areg[it] = *(const float4*)&A[(size_t)(rowBase + aRow0 + it * 16) * EMB + aC4];
    conv_a(areg, 0);
#pragma unroll
    for (int it = 0; it < 8; it++)
        areg[it] = *(const float4*)&A[(size_t)(rowBase + aRow0 + it * 16) * EMB + 64 + aC4];
    cpa_w(0, 0);

    for (int kb = 0; kb < 16; kb++) {
        CP_WAIT(0);
        __syncthreads();

        if (kb < 15) {
            cpa_w(kb + 1, (kb + 1) & 1);
            conv_a(areg, (kb + 1) & 1);
        }
        if (kb < 14) {
            const int k0n = (kb + 2) * 64;
#pragma unroll
            for (int it = 0; it < 8; it++)
                areg[it] = *(const float4*)&A[(size_t)(rowBase + aRow0 + it * 16) * EMB + k0n + aC4];
        }

        const uint32_t sA   = sb + (kb & 1) * PABUF;
        const uint32_t sWhi = sb + (2 + 2 * (kb & 1)) * PABUF;
        warp_gemm_proj(acc, sA, sWhi, sWhi + PABUF, a_lane, b_lane);
    }

    const size_t base = (size_t)tile * TILE_ELE;

    if (p == 0) {
        // Q: hi + lo (split side of GEMM1)
#pragma unroll
        for (int mt = 0; mt < 4; mt++)
#pragma unroll
            for (int nt = 0; nt < 4; nt++) {
                int r0 = mbase + mt * 16 + g;
                int c  = nbase + nt * 8 + t * 2;
                uint32_t hi, lo;
                split2h(acc[mt][nt][0], acc[mt][nt][1], hi, lo);
                *(uint32_t*)(g_q_hi + base + (size_t)r0 * 128 + c) = hi;
                *(uint32_t*)(g_q_lo + base + (size_t)r0 * 128 + c) = lo;
                split2h(acc[mt][nt][2], acc[mt][nt][3], hi, lo);
                *(uint32_t*)(g_q_hi + base + (size_t)(r0 + 8) * 128 + c) = hi;
                *(uint32_t*)(g_q_lo + base + (size_t)(r0 + 8) * 128 + c) = lo;
            }
    } else if (p == 1) {
        // K: hi only
#pragma unroll
        for (int mt = 0; mt < 4; mt++)
#pragma unroll
            for (int nt = 0; nt < 4; nt++) {
                int r0 = mbase + mt * 16 + g;
                int c  = nbase + nt * 8 + t * 2;
                *(uint32_t*)(g_k_hi + base + (size_t)r0 * 128 + c) =
                    cvt2h(acc[mt][nt][0], acc[mt][nt][1]);
                *(uint32_t*)(g_k_hi + base + (size_t)(r0 + 8) * 128 + c) =
                    cvt2h(acc[mt][nt][2], acc[mt][nt][3]);
            }
    } else {
        // V: hi only, transposed [h][n]
#pragma unroll
        for (int mt = 0; mt < 4; mt++)
#pragma unroll
            for (int nt = 0; nt < 4; nt++)
#pragma unroll
                for (int q = 0; q < 4; q++) {
                    int row = mbase + mt * 16 + g + (q >> 1) * 8;   // n index
                    int col = nbase + nt * 8 + t * 2 + (q & 1);     // h index
                    g_v_hi[base + (size_t)col * 128 + row] = __float2half(acc[mt][nt][q]);
                }
    }
}

// ---------------------------------------------------------------------------
// Kernel 2: fused causal retention (fp16, 2-product). Q hi+lo, K/V hi only.
// ---------------------------------------------------------------------------
#define KPAD 136
#define RB (128 * KPAD * 2)
#define SMR_BYTES (4 * RB)          // 139264

__device__ __forceinline__ void cpa_tile(uint32_t dst, const __half* __restrict__ src,
                                         int tid) {
#pragma unroll
    for (int it = 0; it < 8; it++) {
        int u = tid + it * 256;
        int row = u >> 4, c = u & 15;
        CP_ASYNC16(dst + (uint32_t)(row * KPAD + c * 8) * 2, (const char*)src + (size_t)u * 16);
    }
}

__global__ __launch_bounds__(256) void retention_tc(float* __restrict__ out)
{
    extern __shared__ __align__(16) char smraw[];
    const uint32_t sb = smem_u32(smraw);
    const uint32_t sQhi = sb,         sQlo = sb + RB;
    const uint32_t sKhi = sb + 2*RB,  sVhi = sb + 3*RB;

    const int tid  = threadIdx.x;
    const int wid  = tid >> 5, lane = tid & 31;
    const int g    = lane >> 2, t = lane & 3;

    const int b   = blockIdx.x;
    const int cid = blockIdx.y;
    const int qt  = c_qt[cid];
    const int j0  = c_j0[cid];
    const int j1  = c_j1[cid];
    const bool partial = (j1 != qt + 1);
    const int qtile = b * 16 + qt;

    const uint32_t a_lane = (uint32_t)((16 * wid + (lane & 15)) * KPAD + (lane >> 4) * 8) * 2;
    const uint32_t b_lane = (uint32_t)(((lane & 7) + ((lane >> 4) << 3)) * KPAD
                                       + ((lane >> 3) & 1) * 8) * 2;

    cpa_tile(sQhi, g_q_hi + (size_t)qtile * TILE_ELE, tid);
    cpa_tile(sQlo, g_q_lo + (size_t)qtile * TILE_ELE, tid);
    CP_COMMIT();
    {
        const size_t kt = (size_t)(b * 16 + j0) * TILE_ELE;
        cpa_tile(sKhi, g_k_hi + kt, tid);
        CP_COMMIT();
        cpa_tile(sVhi, g_v_hi + kt, tid);
        CP_COMMIT();
    }
    CP_WAIT(1);          // Q + K arrived (V in flight)
    __syncthreads();

    float oacc[16][4];
#pragma unroll
    for (int i = 0; i < 16; i++)
#pragma unroll
        for (int q = 0; q < 4; q++) oacc[i][q] = 0.0f;

    for (int j = j0; j < j1; j++) {
        // ================= GEMM1: S = (Qh+Ql) Kh^T =================
        float sacc[16][4];
#pragma unroll
        for (int i = 0; i < 16; i++)
#pragma unroll
            for (int q = 0; q < 4; q++) sacc[i][q] = 0.0f;

#pragma unroll 2
        for (int ks = 0; ks < 8; ks++) {
            const uint32_t kso = (uint32_t)(ks * 16) * 2;
            uint32_t ah[4], al[4];
            ldm_x4(ah[0], ah[1], ah[2], ah[3], sQhi + a_lane + kso);
            ldm_x4(al[0], al[1], al[2], al[3], sQlo + a_lane + kso);
#pragma unroll
            for (int nb = 0; nb < 8; nb++) {
                const uint32_t boff = b_lane + (uint32_t)(nb * 16 * KPAD) * 2 + kso;
                uint32_t bh[4];
                ldm_x4(bh[0], bh[1], bh[2], bh[3], sKhi + boff);
                mma16816(sacc[2*nb],   ah[0], ah[1], ah[2], ah[3], bh[0], bh[1]);
                mma16816(sacc[2*nb+1], ah[0], ah[1], ah[2], ah[3], bh[2], bh[3]);
                mma16816(sacc[2*nb],   al[0], al[1], al[2], al[3], bh[0], bh[1]);
                mma16816(sacc[2*nb+1], al[0], al[1], al[2], al[3], bh[2], bh[3]);
            }
        }

        if (j == qt) {
            const int r0 = 16 * wid + g;
#pragma unroll
            for (int nt = 0; nt < 16; nt++) {
                const int c0 = nt * 8 + t * 2;
                if (c0     > r0)     sacc[nt][0] = 0.0f;
                if (c0 + 1 > r0)     sacc[nt][1] = 0.0f;
                if (c0     > r0 + 8) sacc[nt][2] = 0.0f;
                if (c0 + 1 > r0 + 8) sacc[nt][3] = 0.0f;
            }
        }

        __syncthreads();            // all warps done reading K(j)
        if (j + 1 < j1) {
            const size_t kt = (size_t)(b * 16 + j + 1) * TILE_ELE;
            cpa_tile(sKhi, g_k_hi + kt, tid);
        }
        CP_COMMIT();                 // group: K(j+1) (possibly empty)
        CP_WAIT(1);                  // V(j) complete
        __syncthreads();

        // ================= GEMM2: O += (Sh+Sl) Vh (S from registers) ========
#pragma unroll
        for (int ks = 0; ks < 8; ks++) {
            uint32_t sh[4], sl[4];
            split2h(sacc[2*ks][0],   sacc[2*ks][1],   sh[0], sl[0]);
            split2h(sacc[2*ks][2],   sacc[2*ks][3],   sh[1], sl[1]);
            split2h(sacc[2*ks+1][0], sacc[2*ks+1][1], sh[2], sl[2]);
            split2h(sacc[2*ks+1][2], sacc[2*ks+1][3], sh[3], sl[3]);
            const uint32_t kso = (uint32_t)(ks * 16) * 2;
#pragma unroll
            for (int hb = 0; hb < 8; hb++) {
                const uint32_t boff = b_lane + (uint32_t)(hb * 16 * KPAD) * 2 + kso;
                uint32_t vh[4];
                ldm_x4(vh[0], vh[1], vh[2], vh[3], sVhi + boff);
                mma16816(oacc[2*hb],   sh[0], sh[1], sh[2], sh[3], vh[0], vh[1]);
                mma16816(oacc[2*hb+1], sh[0], sh[1], sh[2], sh[3], vh[2], vh[3]);
                mma16816(oacc[2*hb],   sl[0], sl[1], sl[2], sl[3], vh[0], vh[1]);
                mma16816(oacc[2*hb+1], sl[0], sl[1], sl[2], sl[3], vh[2], vh[3]);
            }
        }

        __syncthreads();            // all warps done reading V(j)
        if (j + 1 < j1) {
            const size_t kt = (size_t)(b * 16 + j + 1) * TILE_ELE;
            cpa_tile(sVhi, g_v_hi + kt, tid);
        }
        CP_COMMIT();                 // group: V(j+1) (possibly empty)
        CP_WAIT(1);                  // K(j+1) complete
        __syncthreads();
    }

    const int r0 = 16 * wid + g;
    if (!partial) {
        const size_t rowbase = (size_t)b * SEQ + (size_t)qt * 128;
#pragma unroll
        for (int ht = 0; ht < 16; ht++) {
            int c = ht * 8 + t * 2;
            *(float2*)&out[(rowbase + r0) * HEAD + c]     = make_float2(oacc[ht][0], oacc[ht][1]);
            *(float2*)&out[(rowbase + r0 + 8) * HEAD + c] = make_float2(oacc[ht][2], oacc[ht][3]);
        }
    } else {
        float* dst = g_opart + (size_t)(b * 8 + (qt - 8)) * TILE_ELE;
#pragma unroll
        for (int ht = 0; ht < 16; ht++) {
            int c = ht * 8 + t * 2;
            *(float2*)&dst[(size_t)r0 * HEAD + c]       = make_float2(oacc[ht][0], oacc[ht][1]);
            *(float2*)&dst[(size_t)(r0 + 8) * HEAD + c] = make_float2(oacc[ht][2], oacc[ht][3]);
        }
    }
}

// ---------------------------------------------------------------------------
// Kernel 3: add partial O chunks into out (qt >= 8 only). Round-6 version.
// ---------------------------------------------------------------------------
__global__ __launch_bounds__(256) void reduce_partials(float* __restrict__ out)
{
    int gid = blockIdx.x * 256 + threadIdx.x;
    int tile = gid >> 12;
    int w = gid & 4095;
    int b = tile >> 3, qti = tile & 7;
    float4* o = (float4*)(out + ((size_t)b * SEQ + (size_t)(qti + 8) * 128) * HEAD) + w;
    const float4* p = (const float4*)(g_opart + (size_t)tile * TILE_ELE) + w;
    float4 ov = *o, pv = *p;
    ov.x += pv.x; ov.y += pv.y; ov.z += pv.z; ov.w += pv.w;
    *o = ov;
}

// ---------------------------------------------------------------------------
// Launch
// ---------------------------------------------------------------------------
extern "C" void kernel_launch(void* const* d_in, const int* in_sizes, int n_in,
                              void* d_out, int out_size)
{
    const float* key   = (const float*)d_in[0];
    const float* query = (const float*)d_in[1];
    const float* value = (const float*)d_in[2];
    const float* w_q   = (const float*)d_in[3];
    const float* w_k   = (const float*)d_in[4];
    const float* w_v   = (const float*)d_in[5];
    float* out = (float*)d_out;

    prep_w<<<768, 256>>>(w_q, w_k, w_v);

    cudaFuncSetAttribute(proj_tc,
                         cudaFuncAttributeMaxDynamicSharedMemorySize, PSM_TOTAL);
    dim3 g1(NTILES, 3);
    proj_tc<<<g1, 256, PSM_TOTAL>>>(key, query, value);

    cudaFuncSetAttribute(retention_tc,
                         cudaFuncAttributeMaxDynamicSharedMemorySize, SMR_BYTES);
    dim3 g2(BATCH, 24);
    retention_tc<<<g2, 256, SMR_BYTES>>>(out);

    reduce_partials<<<1024, 256>>>(out);
}

// round 10
// speedup vs baseline: 1.9172x; 1.0664x over previous
#include <cuda_runtime.h>
#include <cuda_fp16.h>
#include <cstdint>

// Problem dims
#define BATCH 8
#define SEQ   2048
#define EMB   1024
#define HEAD  128
#define MROWS (BATCH * SEQ)     // 16384
#define NTILES (MROWS / 128)    // 128
#define TILE_ELE (128 * 128)

// fp16 projected tensors, row-major per 128x128 tile.
// Q: hi+lo (split side of GEMM1). K: hi only. V: hi only, TRANSPOSED [h][n].
__device__ __half g_q_hi[NTILES * TILE_ELE];
__device__ __half g_q_lo[NTILES * TILE_ELE];
__device__ __half g_k_hi[NTILES * TILE_ELE];
__device__ __half g_v_hi[NTILES * TILE_ELE];

// Split weights (B side of proj): [w][n][k], k contiguous
__device__ __half g_w_hi[3 * 128 * 1024];
__device__ __half g_w_lo[3 * 128 * 1024];

// Partial O accumulators for split-K chunks (qt >= 8)
__device__ float g_opart[BATCH * 8 * TILE_ELE];

// Chunk schedule (round-6 proven): 24 chunks per batch, longest first.
__constant__ int c_qt[24] = {15,15,14, 7,14,13,13,12, 6,12,11,11,10, 5,10, 9, 9, 8, 4, 8, 3, 2, 1, 0};
__constant__ int c_j0[24] = { 0, 8, 0, 0, 8, 0, 7, 0, 0, 7, 0, 6, 0, 0, 6, 0, 5, 0, 0, 5, 0, 0, 0, 0};
__constant__ int c_j1[24] = { 8,16, 8, 8,15, 7,14, 7, 7,13, 6,12, 6, 6,11, 5,10, 5, 5, 9, 4, 3, 2, 1};

// ---------------------------------------------------------------------------
// PTX helpers (family-generic)
// ---------------------------------------------------------------------------
__device__ __forceinline__ uint32_t smem_u32(const void* p) {
    uint32_t a;
    asm("{ .reg .u64 t; cvta.to.shared.u64 t, %1; cvt.u32.u64 %0, t; }"
        : "=r"(a) : "l"(p));
    return a;
}

__device__ __forceinline__ void mma16816(float* c,
    uint32_t a0, uint32_t a1, uint32_t a2, uint32_t a3,
    uint32_t b0, uint32_t b1)
{
    asm volatile(
        "mma.sync.aligned.m16n8k16.row.col.f32.f16.f16.f32 "
        "{%0,%1,%2,%3}, {%4,%5,%6,%7}, {%8,%9}, {%0,%1,%2,%3};"
        : "+f"(c[0]), "+f"(c[1]), "+f"(c[2]), "+f"(c[3])
        : "r"(a0), "r"(a1), "r"(a2), "r"(a3), "r"(b0), "r"(b1));
}

__device__ __forceinline__ void ldm_x4(uint32_t& r0, uint32_t& r1,
                                       uint32_t& r2, uint32_t& r3, uint32_t addr)
{
    asm volatile("ldmatrix.sync.aligned.m8n8.x4.shared.b16 {%0,%1,%2,%3}, [%4];"
                 : "=r"(r0), "=r"(r1), "=r"(r2), "=r"(r3) : "r"(addr));
}

#define CP_ASYNC16(dst, src) \
    asm volatile("cp.async.cg.shared.global [%0], [%1], 16;" :: "r"(dst), "l"(src))
#define CP_COMMIT() asm volatile("cp.async.commit_group;" ::: "memory")
#define CP_WAIT(n)  asm volatile("cp.async.wait_group %0;" :: "n"(n) : "memory")

// fp16 split: packed hi pair + packed residual pair
__device__ __forceinline__ void split2h(float a0, float a1, uint32_t& hi, uint32_t& lo) {
    __half2 h = __float22half2_rn(make_float2(a0, a1));
    float2 hf = __half22float2(h);
    __half2 l = __float22half2_rn(make_float2(a0 - hf.x, a1 - hf.y));
    hi = *reinterpret_cast<uint32_t*>(&h);
    lo = *reinterpret_cast<uint32_t*>(&l);
}
__device__ __forceinline__ uint32_t cvt2h(float a0, float a1) {
    __half2 h = __float22half2_rn(make_float2(a0, a1));
    return *reinterpret_cast<uint32_t*>(&h);
}

// ---------------------------------------------------------------------------
// Kernel 0: pre-split W into fp16 hi/lo, layout [w][n][k]
// ---------------------------------------------------------------------------
__global__ __launch_bounds__(256) void prep_w(
    const float* __restrict__ wq, const float* __restrict__ wk,
    const float* __restrict__ wv)
{
    int u = blockIdx.x * 256 + threadIdx.x;
    int w = u >> 16;
    int rem = u & 65535;
    int n = rem >> 9;
    int kp = (rem & 511) * 2;
    const float* W = (w == 0) ? wq : (w == 1) ? wk : wv;
    float w0 = W[(size_t)kp * HEAD + n];
    float w1 = W[(size_t)(kp + 1) * HEAD + n];
    uint32_t hi, lo;
    split2h(w0, w1, hi, lo);
    size_t off = ((size_t)w * 128 + n) * 1024 + kp;
    *(uint32_t*)&g_w_hi[off] = hi;
    *(uint32_t*)&g_w_lo[off] = lo;
}

// ---------------------------------------------------------------------------
// Kernel 1: projection GEMM  C = A @ W.  A hi-only (fp16), W hi+lo.
// (Round-9 proven version, unchanged.)
// ---------------------------------------------------------------------------
#define PKPAD 72
#define PABUF (128 * PKPAD * 2)
#define PSM_TOTAL (6 * PABUF)       // 110592

__device__ __forceinline__ void warp_gemm_proj(float acc[4][4][4],
    uint32_t sA, uint32_t sWhi, uint32_t sWlo,
    uint32_t a_lane, uint32_t b_lane)
{
#pragma unroll
    for (int ks = 0; ks < 4; ks++) {
        const uint32_t kso = (uint32_t)(ks * 16) * 2;
        uint32_t ah[4][4];
#pragma unroll
        for (int mt = 0; mt < 4; mt++) {
            const uint32_t ao = a_lane + (uint32_t)(mt * 16 * PKPAD) * 2 + kso;
            ldm_x4(ah[mt][0], ah[mt][1], ah[mt][2], ah[mt][3], sA + ao);
        }
#pragma unroll
        for (int np = 0; np < 2; np++) {
            const uint32_t bo = b_lane + (uint32_t)(np * 16 * PKPAD) * 2 + kso;
            uint32_t bh[4], bl[4];
            ldm_x4(bh[0], bh[1], bh[2], bh[3], sWhi + bo);
            ldm_x4(bl[0], bl[1], bl[2], bl[3], sWlo + bo);
#pragma unroll
            for (int mt = 0; mt < 4; mt++) {
                mma16816(acc[mt][2*np],   ah[mt][0], ah[mt][1], ah[mt][2], ah[mt][3], bh[0], bh[1]);
                mma16816(acc[mt][2*np+1], ah[mt][0], ah[mt][1], ah[mt][2], ah[mt][3], bh[2], bh[3]);
                mma16816(acc[mt][2*np],   ah[mt][0], ah[mt][1], ah[mt][2], ah[mt][3], bl[0], bl[1]);
                mma16816(acc[mt][2*np+1], ah[mt][0], ah[mt][1], ah[mt][2], ah[mt][3], bl[2], bl[3]);
            }
        }
    }
}

__global__ __launch_bounds__(256) void proj_tc(
    const float* __restrict__ in_key,
    const float* __restrict__ in_query,
    const float* __restrict__ in_value)
{
    extern __shared__ __align__(16) char psm[];
    const uint32_t sb = smem_u32(psm);

    const float* A;
    const int p = blockIdx.y;
    if (p == 0)      A = in_query;
    else if (p == 1) A = in_key;
    else             A = in_value;

    const int tid  = threadIdx.x;
    const int wid  = tid >> 5, lane = tid & 31;
    const int g    = lane >> 2, t = lane & 3;
    const int mbase = (wid & 1) * 64;
    const int nbase = (wid >> 1) * 32;
    const int tile = blockIdx.x;
    const int rowBase = tile * 128;

    const uint32_t a_lane = ((mbase + (lane & 15)) * PKPAD + (lane >> 4) * 8) * 2;
    const uint32_t b_lane = ((nbase + (lane & 7) + ((lane >> 4) << 3)) * PKPAD
                             + ((lane >> 3) & 1) * 8) * 2;

    const int aRow0 = tid >> 4;
    const int aC4   = (tid & 15) * 4;

    float acc[4][4][4];
#pragma unroll
    for (int i = 0; i < 4; i++)
#pragma unroll
        for (int j = 0; j < 4; j++)
#pragma unroll
            for (int q = 0; q < 4; q++) acc[i][j][q] = 0.0f;

    const __half* wsrc_hi = g_w_hi + (size_t)p * 128 * 1024;
    const __half* wsrc_lo = g_w_lo + (size_t)p * 128 * 1024;

    auto cpa_w = [&](int kb, int s) {
        uint32_t dhi = sb + (2 + 2 * s) * PABUF;
        uint32_t dlo = dhi + PABUF;
#pragma unroll
        for (int it = 0; it < 4; it++) {
            int u = tid + it * 256;
            int row = u >> 3, c = u & 7;
            uint32_t doff = (uint32_t)(row * PKPAD + c * 8) * 2;
            size_t soff = (size_t)row * 1024 + kb * 64 + c * 8;
            CP_ASYNC16(dhi + doff, (const char*)(wsrc_hi + soff));
            CP_ASYNC16(dlo + doff, (const char*)(wsrc_lo + soff));
        }
        CP_COMMIT();
    };

    auto conv_a = [&](const float4* areg, int s) {
        const uint32_t dA = sb + s * PABUF;
#pragma unroll
        for (int it = 0; it < 8; it++) {
            uint32_t h0 = cvt2h(areg[it].x, areg[it].y);
            uint32_t h1 = cvt2h(areg[it].z, areg[it].w);
            uint32_t doff = (uint32_t)((aRow0 + it * 16) * PKPAD + aC4) * 2;
            asm volatile("st.shared.v2.b32 [%0], {%1,%2};" :: "r"(dA + doff), "r"(h0), "r"(h1));
        }
    };

    float4 areg[8];
#pragma unroll
    for (int it = 0; it < 8; it++)
        areg[it] = *(const float4*)&A[(size_t)(rowBase + aRow0 + it * 16) * EMB + aC4];
    conv_a(areg, 0);
#pragma unroll
    for (int it = 0; it < 8; it++)
        areg[it] = *(const float4*)&A[(size_t)(rowBase + aRow0 + it * 16) * EMB + 64 + aC4];
    cpa_w(0, 0);

    for (int kb = 0; kb < 16; kb++) {
        CP_WAIT(0);
        __syncthreads();

        if (kb < 15) {
            cpa_w(kb + 1, (kb + 1) & 1);
            conv_a(areg, (kb + 1) & 1);
        }
        if (kb < 14) {
            const int k0n = (kb + 2) * 64;
#pragma unroll
            for (int it = 0; it < 8; it++)
                areg[it] = *(const float4*)&A[(size_t)(rowBase + aRow0 + it * 16) * EMB + k0n + aC4];
        }

        const uint32_t sA   = sb + (kb & 1) * PABUF;
        const uint32_t sWhi = sb + (2 + 2 * (kb & 1)) * PABUF;
        warp_gemm_proj(acc, sA, sWhi, sWhi + PABUF, a_lane, b_lane);
    }

    const size_t base = (size_t)tile * TILE_ELE;

    if (p == 0) {
        // Q: hi + lo (split side of GEMM1)
#pragma unroll
        for (int mt = 0; mt < 4; mt++)
#pragma unroll
            for (int nt = 0; nt < 4; nt++) {
                int r0 = mbase + mt * 16 + g;
                int c  = nbase + nt * 8 + t * 2;
                uint32_t hi, lo;
                split2h(acc[mt][nt][0], acc[mt][nt][1], hi, lo);
                *(uint32_t*)(g_q_hi + base + (size_t)r0 * 128 + c) = hi;
                *(uint32_t*)(g_q_lo + base + (size_t)r0 * 128 + c) = lo;
                split2h(acc[mt][nt][2], acc[mt][nt][3], hi, lo);
                *(uint32_t*)(g_q_hi + base + (size_t)(r0 + 8) * 128 + c) = hi;
                *(uint32_t*)(g_q_lo + base + (size_t)(r0 + 8) * 128 + c) = lo;
            }
    } else if (p == 1) {
        // K: hi only
#pragma unroll
        for (int mt = 0; mt < 4; mt++)
#pragma unroll
            for (int nt = 0; nt < 4; nt++) {
                int r0 = mbase + mt * 16 + g;
                int c  = nbase + nt * 8 + t * 2;
                *(uint32_t*)(g_k_hi + base + (size_t)r0 * 128 + c) =
                    cvt2h(acc[mt][nt][0], acc[mt][nt][1]);
                *(uint32_t*)(g_k_hi + base + (size_t)(r0 + 8) * 128 + c) =
                    cvt2h(acc[mt][nt][2], acc[mt][nt][3]);
            }
    } else {
        // V: hi only, transposed [h][n]
#pragma unroll
        for (int mt = 0; mt < 4; mt++)
#pragma unroll
            for (int nt = 0; nt < 4; nt++)
#pragma unroll
                for (int q = 0; q < 4; q++) {
                    int row = mbase + mt * 16 + g + (q >> 1) * 8;   // n index
                    int col = nbase + nt * 8 + t * 2 + (q & 1);     // h index
                    g_v_hi[base + (size_t)col * 128 + row] = __float2half(acc[mt][nt][q]);
                }
    }
}

// ---------------------------------------------------------------------------
// Kernel 2: fused causal retention.
// Q hi+lo; K/V hi only, DOUBLE-BUFFERED. One sync + one wait per iteration;
// GEMM1 -> mask -> GEMM2 run back-to-back with no barriers (S in registers).
// GEMM2 is single-product (S-hi only).
// ---------------------------------------------------------------------------
#define KPAD 136
#define RB (128 * KPAD * 2)
#define SMR_BYTES (6 * RB)          // 208896: Qhi, Qlo, K0, K1, V0, V1

__device__ __forceinline__ void cpa_tile(uint32_t dst, const __half* __restrict__ src,
                                         int tid) {
#pragma unroll
    for (int it = 0; it < 8; it++) {
        int u = tid + it * 256;
        int row = u >> 4, c = u & 15;
        CP_ASYNC16(dst + (uint32_t)(row * KPAD + c * 8) * 2, (const char*)src + (size_t)u * 16);
    }
}

__global__ __launch_bounds__(256) void retention_tc(float* __restrict__ out)
{
    extern __shared__ __align__(16) char smraw[];
    const uint32_t sb = smem_u32(smraw);
    const uint32_t sQhi = sb,        sQlo = sb + RB;
    const uint32_t sK0  = sb + 2*RB; // K stage base (stage s at sK0 + s*RB)
    const uint32_t sV0  = sb + 4*RB; // V stage base

    const int tid  = threadIdx.x;
    const int wid  = tid >> 5, lane = tid & 31;
    const int g    = lane >> 2, t = lane & 3;

    const int b   = blockIdx.x;
    const int cid = blockIdx.y;
    const int qt  = c_qt[cid];
    const int j0  = c_j0[cid];
    const int j1  = c_j1[cid];
    const bool partial = (j1 != qt + 1);
    const int qtile = b * 16 + qt;

    const uint32_t a_lane = (uint32_t)((16 * wid + (lane & 15)) * KPAD + (lane >> 4) * 8) * 2;
    const uint32_t b_lane = (uint32_t)(((lane & 7) + ((lane >> 4) << 3)) * KPAD
                                       + ((lane >> 3) & 1) * 8) * 2;

    // Prologue: Q + K(j0) + V(j0) as ONE group, into stage j0&1.
    cpa_tile(sQhi, g_q_hi + (size_t)qtile * TILE_ELE, tid);
    cpa_tile(sQlo, g_q_lo + (size_t)qtile * TILE_ELE, tid);
    {
        const size_t kt = (size_t)(b * 16 + j0) * TILE_ELE;
        cpa_tile(sK0 + (uint32_t)(j0 & 1) * RB, g_k_hi + kt, tid);
        cpa_tile(sV0 + (uint32_t)(j0 & 1) * RB, g_v_hi + kt, tid);
    }
    CP_COMMIT();
    CP_WAIT(0);
    __syncthreads();

    float oacc[16][4];
#pragma unroll
    for (int i = 0; i < 16; i++)
#pragma unroll
        for (int q = 0; q < 4; q++) oacc[i][q] = 0.0f;

    for (int j = j0; j < j1; j++) {
        // Issue next K/V into the other stage. That stage was last read at
        // iteration j-1, sealed by the barrier at the end of j-1.
        if (j + 1 < j1) {
            const size_t kt = (size_t)(b * 16 + j + 1) * TILE_ELE;
            cpa_tile(sK0 + (uint32_t)((j + 1) & 1) * RB, g_k_hi + kt, tid);
            cpa_tile(sV0 + (uint32_t)((j + 1) & 1) * RB, g_v_hi + kt, tid);
            CP_COMMIT();
        }

        const uint32_t sKc = sK0 + (uint32_t)(j & 1) * RB;
        const uint32_t sVc = sV0 + (uint32_t)(j & 1) * RB;

        // ================= GEMM1: S = (Qh+Ql) Kh^T =================
        float sacc[16][4];
#pragma unroll
        for (int i = 0; i < 16; i++)
#pragma unroll
            for (int q = 0; q < 4; q++) sacc[i][q] = 0.0f;

#pragma unroll 2
        for (int ks = 0; ks < 8; ks++) {
            const uint32_t kso = (uint32_t)(ks * 16) * 2;
            uint32_t ah[4], al[4];
            ldm_x4(ah[0], ah[1], ah[2], ah[3], sQhi + a_lane + kso);
            ldm_x4(al[0], al[1], al[2], al[3], sQlo + a_lane + kso);
#pragma unroll
            for (int nb = 0; nb < 8; nb++) {
                const uint32_t boff = b_lane + (uint32_t)(nb * 16 * KPAD) * 2 + kso;
                uint32_t bh[4];
                ldm_x4(bh[0], bh[1], bh[2], bh[3], sKc + boff);
                mma16816(sacc[2*nb],   ah[0], ah[1], ah[2], ah[3], bh[0], bh[1]);
                mma16816(sacc[2*nb+1], ah[0], ah[1], ah[2], ah[3], bh[2], bh[3]);
                mma16816(sacc[2*nb],   al[0], al[1], al[2], al[3], bh[0], bh[1]);
                mma16816(sacc[2*nb+1], al[0], al[1], al[2], al[3], bh[2], bh[3]);
            }
        }

        // ---- causal mask on diagonal tile ----
        if (j == qt) {
            const int r0 = 16 * wid + g;
#pragma unroll
            for (int nt = 0; nt < 16; nt++) {
                const int c0 = nt * 8 + t * 2;
                if (c0     > r0)     sacc[nt][0] = 0.0f;
                if (c0 + 1 > r0)     sacc[nt][1] = 0.0f;
                if (c0     > r0 + 8) sacc[nt][2] = 0.0f;
                if (c0 + 1 > r0 + 8) sacc[nt][3] = 0.0f;
            }
        }

        // ================= GEMM2: O += Sh Vh (single product) ===============
        // No barrier needed: S is in registers, V(j) was loaded last iteration.
#pragma unroll
        for (int ks = 0; ks < 8; ks++) {
            uint32_t sh[4];
            sh[0] = cvt2h(sacc[2*ks][0],   sacc[2*ks][1]);
            sh[1] = cvt2h(sacc[2*ks][2],   sacc[2*ks][3]);
            sh[2] = cvt2h(sacc[2*ks+1][0], sacc[2*ks+1][1]);
            sh[3] = cvt2h(sacc[2*ks+1][2], sacc[2*ks+1][3]);
            const uint32_t kso = (uint32_t)(ks * 16) * 2;
#pragma unroll
            for (int hb = 0; hb < 8; hb++) {
                const uint32_t boff = b_lane + (uint32_t)(hb * 16 * KPAD) * 2 + kso;
                uint32_t vh[4];
                ldm_x4(vh[0], vh[1], vh[2], vh[3], sVc + boff);
                mma16816(oacc[2*hb],   sh[0], sh[1], sh[2], sh[3], vh[0], vh[1]);
                mma16816(oacc[2*hb+1], sh[0], sh[1], sh[2], sh[3], vh[2], vh[3]);
            }
        }

        // Close the iteration: next-stage loads complete + visible to all.
        if (j + 1 < j1) {
            CP_WAIT(0);
            __syncthreads();
        }
    }

    const int r0 = 16 * wid + g;
    if (!partial) {
        const size_t rowbase = (size_t)b * SEQ + (size_t)qt * 128;
#pragma unroll
        for (int ht = 0; ht < 16; ht++) {
            int c = ht * 8 + t * 2;
            *(float2*)&out[(rowbase + r0) * HEAD + c]     = make_float2(oacc[ht][0], oacc[ht][1]);
            *(float2*)&out[(rowbase + r0 + 8) * HEAD + c] = make_float2(oacc[ht][2], oacc[ht][3]);
        }
    } else {
        float* dst = g_opart + (size_t)(b * 8 + (qt - 8)) * TILE_ELE;
#pragma unroll
        for (int ht = 0; ht < 16; ht++) {
            int c = ht * 8 + t * 2;
            *(float2*)&dst[(size_t)r0 * HEAD + c]       = make_float2(oacc[ht][0], oacc[ht][1]);
            *(float2*)&dst[(size_t)(r0 + 8) * HEAD + c] = make_float2(oacc[ht][2], oacc[ht][3]);
        }
    }
}

// ---------------------------------------------------------------------------
// Kernel 3: add partial O chunks into out (qt >= 8 only).
// ---------------------------------------------------------------------------
__global__ __launch_bounds__(256) void reduce_partials(float* __restrict__ out)
{
    int gid = blockIdx.x * 256 + threadIdx.x;
    int tile = gid >> 12;
    int w = gid & 4095;
    int b = tile >> 3, qti = tile & 7;
    float4* o = (float4*)(out + ((size_t)b * SEQ + (size_t)(qti + 8) * 128) * HEAD) + w;
    const float4* p = (const float4*)(g_opart + (size_t)tile * TILE_ELE) + w;
    float4 ov = *o, pv = *p;
    ov.x += pv.x; ov.y += pv.y; ov.z += pv.z; ov.w += pv.w;
    *o = ov;
}

// ---------------------------------------------------------------------------
// Launch
// ---------------------------------------------------------------------------
extern "C" void kernel_launch(void* const* d_in, const int* in_sizes, int n_in,
                              void* d_out, int out_size)
{
    const float* key   = (const float*)d_in[0];
    const float* query = (const float*)d_in[1];
    const float* value = (const float*)d_in[2];
    const float* w_q   = (const float*)d_in[3];
    const float* w_k   = (const float*)d_in[4];
    const float* w_v   = (const float*)d_in[5];
    float* out = (float*)d_out;

    prep_w<<<768, 256>>>(w_q, w_k, w_v);

    cudaFuncSetAttribute(proj_tc,
                         cudaFuncAttributeMaxDynamicSharedMemorySize, PSM_TOTAL);
    dim3 g1(NTILES, 3);
    proj_tc<<<g1, 256, PSM_TOTAL>>>(key, query, value);

    cudaFuncSetAttribute(retention_tc,
                         cudaFuncAttributeMaxDynamicSharedMemorySize, SMR_BYTES);
    dim3 g2(BATCH, 24);
    retention_tc<<<g2, 256, SMR_BYTES>>>(out);

    reduce_partials<<<1024, 256>>>(out);
}

// round 11
// speedup vs baseline: 2.7030x; 1.4099x over previous
#include <cuda_runtime.h>
#include <cuda_fp16.h>
#include <cstdint>

// Problem dims
#define BATCH 8
#define SEQ   2048
#define EMB   1024
#define HEAD  128
#define MROWS (BATCH * SEQ)     // 16384
#define NTILES (MROWS / 128)    // 128
#define TILE_ELE (128 * 128)

// fp16 projected tensors, row-major per 128x128 tile.
// Q: [m][h]. K: [n][h]. V: TRANSPOSED [h][n]. All hi-only fp16.
__device__ __half g_q[NTILES * TILE_ELE];
__device__ __half g_k[NTILES * TILE_ELE];
__device__ __half g_v[NTILES * TILE_ELE];

// fp16 weights: [w][n][k], k contiguous
__device__ __half g_w[3 * 128 * 1024];

// Partial O accumulators for split-K chunks (qt >= 8)
__device__ float g_opart[BATCH * 8 * TILE_ELE];

// Chunk schedule (round-6 proven): 24 chunks per batch, longest first.
__constant__ int c_qt[24] = {15,15,14, 7,14,13,13,12, 6,12,11,11,10, 5,10, 9, 9, 8, 4, 8, 3, 2, 1, 0};
__constant__ int c_j0[24] = { 0, 8, 0, 0, 8, 0, 7, 0, 0, 7, 0, 6, 0, 0, 6, 0, 5, 0, 0, 5, 0, 0, 0, 0};
__constant__ int c_j1[24] = { 8,16, 8, 8,15, 7,14, 7, 7,13, 6,12, 6, 6,11, 5,10, 5, 5, 9, 4, 3, 2, 1};

// ---------------------------------------------------------------------------
// PTX helpers (family-generic)
// ---------------------------------------------------------------------------
__device__ __forceinline__ uint32_t smem_u32(const void* p) {
    uint32_t a;
    asm("{ .reg .u64 t; cvta.to.shared.u64 t, %1; cvt.u32.u64 %0, t; }"
        : "=r"(a) : "l"(p));
    return a;
}

__device__ __forceinline__ void mma16816(float* c,
    uint32_t a0, uint32_t a1, uint32_t a2, uint32_t a3,
    uint32_t b0, uint32_t b1)
{
    asm volatile(
        "mma.sync.aligned.m16n8k16.row.col.f32.f16.f16.f32 "
        "{%0,%1,%2,%3}, {%4,%5,%6,%7}, {%8,%9}, {%0,%1,%2,%3};"
        : "+f"(c[0]), "+f"(c[1]), "+f"(c[2]), "+f"(c[3])
        : "r"(a0), "r"(a1), "r"(a2), "r"(a3), "r"(b0), "r"(b1));
}

__device__ __forceinline__ void ldm_x4(uint32_t& r0, uint32_t& r1,
                                       uint32_t& r2, uint32_t& r3, uint32_t addr)
{
    asm volatile("ldmatrix.sync.aligned.m8n8.x4.shared.b16 {%0,%1,%2,%3}, [%4];"
                 : "=r"(r0), "=r"(r1), "=r"(r2), "=r"(r3) : "r"(addr));
}

#define CP_ASYNC16(dst, src) \
    asm volatile("cp.async.cg.shared.global [%0], [%1], 16;" :: "r"(dst), "l"(src))
#define CP_COMMIT() asm volatile("cp.async.commit_group;" ::: "memory")
#define CP_WAIT(n)  asm volatile("cp.async.wait_group %0;" :: "n"(n) : "memory")

__device__ __forceinline__ uint32_t cvt2h(float a0, float a1) {
    __half2 h = __float22half2_rn(make_float2(a0, a1));
    return *reinterpret_cast<uint32_t*>(&h);
}

// ---------------------------------------------------------------------------
// Kernel 0: convert W to fp16, layout [w][n][k]
// ---------------------------------------------------------------------------
__global__ __launch_bounds__(256) void prep_w(
    const float* __restrict__ wq, const float* __restrict__ wk,
    const float* __restrict__ wv)
{
    int u = blockIdx.x * 256 + threadIdx.x;
    int w = u >> 16;
    int rem = u & 65535;
    int n = rem >> 9;
    int kp = (rem & 511) * 2;
    const float* W = (w == 0) ? wq : (w == 1) ? wk : wv;
    float w0 = W[(size_t)kp * HEAD + n];
    float w1 = W[(size_t)(kp + 1) * HEAD + n];
    *(uint32_t*)&g_w[((size_t)w * 128 + n) * 1024 + kp] = cvt2h(w0, w1);
}

// ---------------------------------------------------------------------------
// Kernel 1: projection GEMM  C = A @ W, pure fp16 single-product.
// A double-buffered via regs+STS, W double-buffered cp.async.
// Per ks-step: 16 mma on 16 distinct accumulators (RAW distance 16).
// ---------------------------------------------------------------------------
#define PKPAD 72
#define PABUF (128 * PKPAD * 2)
// smem: A0 0, A1 1, W0 2, W1 3
#define PSM_TOTAL (4 * PABUF)       // 73728

__device__ __forceinline__ void warp_gemm_proj(float acc[4][4][4],
    uint32_t sA, uint32_t sW, uint32_t a_lane, uint32_t b_lane)
{
#pragma unroll
    for (int ks = 0; ks < 4; ks++) {
        const uint32_t kso = (uint32_t)(ks * 16) * 2;
        uint32_t ah[4][4];
#pragma unroll
        for (int mt = 0; mt < 4; mt++) {
            const uint32_t ao = a_lane + (uint32_t)(mt * 16 * PKPAD) * 2 + kso;
            ldm_x4(ah[mt][0], ah[mt][1], ah[mt][2], ah[mt][3], sA + ao);
        }
#pragma unroll
        for (int np = 0; np < 2; np++) {
            const uint32_t bo = b_lane + (uint32_t)(np * 16 * PKPAD) * 2 + kso;
            uint32_t bh[4];
            ldm_x4(bh[0], bh[1], bh[2], bh[3], sW + bo);
#pragma unroll
            for (int mt = 0; mt < 4; mt++) {
                mma16816(acc[mt][2*np],   ah[mt][0], ah[mt][1], ah[mt][2], ah[mt][3], bh[0], bh[1]);
                mma16816(acc[mt][2*np+1], ah[mt][0], ah[mt][1], ah[mt][2], ah[mt][3], bh[2], bh[3]);
            }
        }
    }
}

__global__ __launch_bounds__(256) void proj_tc(
    const float* __restrict__ in_key,
    const float* __restrict__ in_query,
    const float* __restrict__ in_value)
{
    extern __shared__ __align__(16) char psm[];
    const uint32_t sb = smem_u32(psm);

    const float* A;
    const int p = blockIdx.y;
    if (p == 0)      A = in_query;
    else if (p == 1) A = in_key;
    else             A = in_value;

    const int tid  = threadIdx.x;
    const int wid  = tid >> 5, lane = tid & 31;
    const int g    = lane >> 2, t = lane & 3;
    const int mbase = (wid & 1) * 64;
    const int nbase = (wid >> 1) * 32;
    const int tile = blockIdx.x;
    const int rowBase = tile * 128;

    const uint32_t a_lane = ((mbase + (lane & 15)) * PKPAD + (lane >> 4) * 8) * 2;
    const uint32_t b_lane = ((nbase + (lane & 7) + ((lane >> 4) << 3)) * PKPAD
                             + ((lane >> 3) & 1) * 8) * 2;

    const int aRow0 = tid >> 4;
    const int aC4   = (tid & 15) * 4;

    float acc[4][4][4];
#pragma unroll
    for (int i = 0; i < 4; i++)
#pragma unroll
        for (int j = 0; j < 4; j++)
#pragma unroll
            for (int q = 0; q < 4; q++) acc[i][j][q] = 0.0f;

    const __half* wsrc = g_w + (size_t)p * 128 * 1024;

    auto cpa_w = [&](int kb, int s) {
        uint32_t dw = sb + (2 + s) * PABUF;
#pragma unroll
        for (int it = 0; it < 4; it++) {
            int u = tid + it * 256;
            int row = u >> 3, c = u & 7;
            uint32_t doff = (uint32_t)(row * PKPAD + c * 8) * 2;
            size_t soff = (size_t)row * 1024 + kb * 64 + c * 8;
            CP_ASYNC16(dw + doff, (const char*)(wsrc + soff));
        }
        CP_COMMIT();
    };

    auto conv_a = [&](const float4* areg, int s) {
        const uint32_t dA = sb + s * PABUF;
#pragma unroll
        for (int it = 0; it < 8; it++) {
            uint32_t h0 = cvt2h(areg[it].x, areg[it].y);
            uint32_t h1 = cvt2h(areg[it].z, areg[it].w);
            uint32_t doff = (uint32_t)((aRow0 + it * 16) * PKPAD + aC4) * 2;
            asm volatile("st.shared.v2.b32 [%0], {%1,%2};" :: "r"(dA + doff), "r"(h0), "r"(h1));
        }
    };

    float4 areg[8];
#pragma unroll
    for (int it = 0; it < 8; it++)
        areg[it] = *(const float4*)&A[(size_t)(rowBase + aRow0 + it * 16) * EMB + aC4];
    conv_a(areg, 0);
#pragma unroll
    for (int it = 0; it < 8; it++)
        areg[it] = *(const float4*)&A[(size_t)(rowBase + aRow0 + it * 16) * EMB + 64 + aC4];
    cpa_w(0, 0);

    for (int kb = 0; kb < 16; kb++) {
        CP_WAIT(0);
        __syncthreads();

        if (kb < 15) {
            cpa_w(kb + 1, (kb + 1) & 1);
            conv_a(areg, (kb + 1) & 1);
        }
        if (kb < 14) {
            const int k0n = (kb + 2) * 64;
#pragma unroll
            for (int it = 0; it < 8; it++)
                areg[it] = *(const float4*)&A[(size_t)(rowBase + aRow0 + it * 16) * EMB + k0n + aC4];
        }

        const uint32_t sA = sb + (kb & 1) * PABUF;
        const uint32_t sW = sb + (2 + (kb & 1)) * PABUF;
        warp_gemm_proj(acc, sA, sW, a_lane, b_lane);
    }

    const size_t base = (size_t)tile * TILE_ELE;

    if (p != 2) {
        // Q / K: natural [row][h], fp16
        __half* dst = (p == 0) ? g_q : g_k;
#pragma unroll
        for (int mt = 0; mt < 4; mt++)
#pragma unroll
            for (int nt = 0; nt < 4; nt++) {
                int r0 = mbase + mt * 16 + g;
                int c  = nbase + nt * 8 + t * 2;
                *(uint32_t*)(dst + base + (size_t)r0 * 128 + c) =
                    cvt2h(acc[mt][nt][0], acc[mt][nt][1]);
                *(uint32_t*)(dst + base + (size_t)(r0 + 8) * 128 + c) =
                    cvt2h(acc[mt][nt][2], acc[mt][nt][3]);
            }
    } else {
        // V: transposed [h][n]
#pragma unroll
        for (int mt = 0; mt < 4; mt++)
#pragma unroll
            for (int nt = 0; nt < 4; nt++)
#pragma unroll
                for (int q = 0; q < 4; q++) {
                    int row = mbase + mt * 16 + g + (q >> 1) * 8;   // n index
                    int col = nbase + nt * 8 + t * 2 + (q & 1);     // h index
                    g_v[base + (size_t)col * 128 + row] = __float2half(acc[mt][nt][q]);
                }
    }
}

// ---------------------------------------------------------------------------
// Kernel 2: fused causal retention, pure fp16 single-product.
// Q resident; K/V double-buffered; GEMM1 -> mask -> GEMM2 barrier-free
// (S in registers). Every ks-step: 16 mma on 16 distinct accumulators.
// ---------------------------------------------------------------------------
#define KPAD 136
#define RB (128 * KPAD * 2)
#define SMR_BYTES (5 * RB)          // 174080: Q, K0, K1, V0, V1

__device__ __forceinline__ void cpa_tile(uint32_t dst, const __half* __restrict__ src,
                                         int tid) {
#pragma unroll
    for (int it = 0; it < 8; it++) {
        int u = tid + it * 256;
        int row = u >> 4, c = u & 15;
        CP_ASYNC16(dst + (uint32_t)(row * KPAD + c * 8) * 2, (const char*)src + (size_t)u * 16);
    }
}

__global__ __launch_bounds__(256) void retention_tc(float* __restrict__ out)
{
    extern __shared__ __align__(16) char smraw[];
    const uint32_t sb = smem_u32(smraw);
    const uint32_t sQ  = sb;
    const uint32_t sK0 = sb + RB;       // K stage s at sK0 + s*RB
    const uint32_t sV0 = sb + 3*RB;     // V stage s at sV0 + s*RB

    const int tid  = threadIdx.x;
    const int wid  = tid >> 5, lane = tid & 31;
    const int g    = lane >> 2, t = lane & 3;

    const int b   = blockIdx.x;
    const int cid = blockIdx.y;
    const int qt  = c_qt[cid];
    const int j0  = c_j0[cid];
    const int j1  = c_j1[cid];
    const bool partial = (j1 != qt + 1);
    const int qtile = b * 16 + qt;

    const uint32_t a_lane = (uint32_t)((16 * wid + (lane & 15)) * KPAD + (lane >> 4) * 8) * 2;
    const uint32_t b_lane = (uint32_t)(((lane & 7) + ((lane >> 4) << 3)) * KPAD
                                       + ((lane >> 3) & 1) * 8) * 2;

    // Prologue: Q + K(j0) + V(j0) as one group, into stage j0&1.
    cpa_tile(sQ, g_q + (size_t)qtile * TILE_ELE, tid);
    {
        const size_t kt = (size_t)(b * 16 + j0) * TILE_ELE;
        cpa_tile(sK0 + (uint32_t)(j0 & 1) * RB, g_k + kt, tid);
        cpa_tile(sV0 + (uint32_t)(j0 & 1) * RB, g_v + kt, tid);
    }
    CP_COMMIT();
    CP_WAIT(0);
    __syncthreads();

    float oacc[16][4];
#pragma unroll
    for (int i = 0; i < 16; i++)
#pragma unroll
        for (int q = 0; q < 4; q++) oacc[i][q] = 0.0f;

    for (int j = j0; j < j1; j++) {
        if (j + 1 < j1) {
            const size_t kt = (size_t)(b * 16 + j + 1) * TILE_ELE;
            cpa_tile(sK0 + (uint32_t)((j + 1) & 1) * RB, g_k + kt, tid);
            cpa_tile(sV0 + (uint32_t)((j + 1) & 1) * RB, g_v + kt, tid);
            CP_COMMIT();
        }

        const uint32_t sKc = sK0 + (uint32_t)(j & 1) * RB;
        const uint32_t sVc = sV0 + (uint32_t)(j & 1) * RB;

        // ================= GEMM1: S = Q K^T (single product) ================
        float sacc[16][4];
#pragma unroll
        for (int i = 0; i < 16; i++)
#pragma unroll
            for (int q = 0; q < 4; q++) sacc[i][q] = 0.0f;

#pragma unroll 2
        for (int ks = 0; ks < 8; ks++) {
            const uint32_t kso = (uint32_t)(ks * 16) * 2;
            uint32_t ah[4];
            ldm_x4(ah[0], ah[1], ah[2], ah[3], sQ + a_lane + kso);
#pragma unroll
            for (int nb = 0; nb < 8; nb++) {
                const uint32_t boff = b_lane + (uint32_t)(nb * 16 * KPAD) * 2 + kso;
                uint32_t bh[4];
                ldm_x4(bh[0], bh[1], bh[2], bh[3], sKc + boff);
                mma16816(sacc[2*nb],   ah[0], ah[1], ah[2], ah[3], bh[0], bh[1]);
                mma16816(sacc[2*nb+1], ah[0], ah[1], ah[2], ah[3], bh[2], bh[3]);
            }
        }

        // ---- causal mask on diagonal tile ----
        if (j == qt) {
            const int r0 = 16 * wid + g;
#pragma unroll
            for (int nt = 0; nt < 16; nt++) {
                const int c0 = nt * 8 + t * 2;
                if (c0     > r0)     sacc[nt][0] = 0.0f;
                if (c0 + 1 > r0)     sacc[nt][1] = 0.0f;
                if (c0     > r0 + 8) sacc[nt][2] = 0.0f;
                if (c0 + 1 > r0 + 8) sacc[nt][3] = 0.0f;
            }
        }

        // ================= GEMM2: O += S V (single product, S in regs) ======
#pragma unroll
        for (int ks = 0; ks < 8; ks++) {
            uint32_t sh[4];
            sh[0] = cvt2h(sacc[2*ks][0],   sacc[2*ks][1]);
            sh[1] = cvt2h(sacc[2*ks][2],   sacc[2*ks][3]);
            sh[2] = cvt2h(sacc[2*ks+1][0], sacc[2*ks+1][1]);
            sh[3] = cvt2h(sacc[2*ks+1][2], sacc[2*ks+1][3]);
            const uint32_t kso = (uint32_t)(ks * 16) * 2;
#pragma unroll
            for (int hb = 0; hb < 8; hb++) {
                const uint32_t boff = b_lane + (uint32_t)(hb * 16 * KPAD) * 2 + kso;
                uint32_t vh[4];
                ldm_x4(vh[0], vh[1], vh[2], vh[3], sVc + boff);
                mma16816(oacc[2*hb],   sh[0], sh[1], sh[2], sh[3], vh[0], vh[1]);
                mma16816(oacc[2*hb+1], sh[0], sh[1], sh[2], sh[3], vh[2], vh[3]);
            }
        }

        if (j + 1 < j1) {
            CP_WAIT(0);
            __syncthreads();
        }
    }

    const int r0 = 16 * wid + g;
    if (!partial) {
        const size_t rowbase = (size_t)b * SEQ + (size_t)qt * 128;
#pragma unroll
        for (int ht = 0; ht < 16; ht++) {
            int c = ht * 8 + t * 2;
            *(float2*)&out[(rowbase + r0) * HEAD + c]     = make_float2(oacc[ht][0], oacc[ht][1]);
            *(float2*)&out[(rowbase + r0 + 8) * HEAD + c] = make_float2(oacc[ht][2], oacc[ht][3]);
        }
    } else {
        float* dst = g_opart + (size_t)(b * 8 + (qt - 8)) * TILE_ELE;
#pragma unroll
        for (int ht = 0; ht < 16; ht++) {
            int c = ht * 8 + t * 2;
            *(float2*)&dst[(size_t)r0 * HEAD + c]       = make_float2(oacc[ht][0], oacc[ht][1]);
            *(float2*)&dst[(size_t)(r0 + 8) * HEAD + c] = make_float2(oacc[ht][2], oacc[ht][3]);
        }
    }
}

// ---------------------------------------------------------------------------
// Kernel 3: add partial O chunks into out (qt >= 8 only).
// ---------------------------------------------------------------------------
__global__ __launch_bounds__(256) void reduce_partials(float* __restrict__ out)
{
    int gid = blockIdx.x * 256 + threadIdx.x;
    int tile = gid >> 12;
    int w = gid & 4095;
    int b = tile >> 3, qti = tile & 7;
    float4* o = (float4*)(out + ((size_t)b * SEQ + (size_t)(qti + 8) * 128) * HEAD) + w;
    const float4* p = (const float4*)(g_opart + (size_t)tile * TILE_ELE) + w;
    float4 ov = *o, pv = *p;
    ov.x += pv.x; ov.y += pv.y; ov.z += pv.z; ov.w += pv.w;
    *o = ov;
}

// ---------------------------------------------------------------------------
// Launch
// ---------------------------------------------------------------------------
extern "C" void kernel_launch(void* const* d_in, const int* in_sizes, int n_in,
                              void* d_out, int out_size)
{
    const float* key   = (const float*)d_in[0];
    const float* query = (const float*)d_in[1];
    const float* value = (const float*)d_in[2];
    const float* w_q   = (const float*)d_in[3];
    const float* w_k   = (const float*)d_in[4];
    const float* w_v   = (const float*)d_in[5];
    float* out = (float*)d_out;

    prep_w<<<768, 256>>>(w_q, w_k, w_v);

    cudaFuncSetAttribute(proj_tc,
                         cudaFuncAttributeMaxDynamicSharedMemorySize, PSM_TOTAL);
    dim3 g1(NTILES, 3);
    proj_tc<<<g1, 256, PSM_TOTAL>>>(key, query, value);

    cudaFuncSetAttribute(retention_tc,
                         cudaFuncAttributeMaxDynamicSharedMemorySize, SMR_BYTES);
    dim3 g2(BATCH, 24);
    retention_tc<<<g2, 256, SMR_BYTES>>>(out);

    reduce_partials<<<1024, 256>>>(out);
}